// round 9
// baseline (speedup 1.0000x reference)
#include <cuda_runtime.h>
#include <math.h>

#define BATCH  2048
#define DIN    2048
#define DB     256
#define NHIST  63488
#define NBANK  (BATCH + NHIST)
#define NC     31

typedef unsigned long long ull;

__device__ float g_tf[BATCH * DB];
__device__ float g_bns[(size_t)NBANK * DB];    /* normalized bank rows (unsorted) */
__device__ float g_dT[(size_t)NBANK * BATCH];  /* 512MB: fl(1-dot), [col][b] */
__device__ float g_dist[BATCH * 32];
__device__ int   g_idx[NBANK];                 /* class-sorted -> original row */
__device__ int   g_cofs[NC + 1];
__device__ int   g_bh[256 * NC];
__device__ int   g_base[256 * NC];
__device__ int   g_ltar[BATCH];
__device__ float g_loss[BATCH];
__device__ int   g_lab64;

__device__ __forceinline__ int get_lab(const int* p, int i) {
    return g_lab64 ? p[2 * i] : p[i];
}
__device__ __forceinline__ int bank_lab(const int* cl, const int* hl, int i) {
    return (i < BATCH) ? get_lab(cl, i) : get_lab(hl, i - BATCH);
}
__device__ __forceinline__ void ffma2(ull& d, ull a, ull b) {
    asm("fma.rn.f32x2 %0, %1, %2, %0;" : "+l"(d) : "l"(a), "l"(b));
}
__device__ __forceinline__ float2 unpack2(ull v) {
    float2 f;
    asm("mov.b64 {%0, %1}, %2;" : "=f"(f.x), "=f"(f.y) : "l"(v));
    return f;
}

/* ---- L1: label dtype detect ---- */
__global__ void k_init(const int* __restrict__ curlab) {
    if (threadIdx.x == 0) {
        int z = 1;
        for (int i = 1; i < 32; i += 2)
            if (curlab[i] != 0) z = 0;
        g_lab64 = z;
    }
}

/* ---- L2: tf = relu(target@W1+b1), sequential-k FMA chains ---- */
#define BM 64
#define BN 64
#define BK 16
__device__ __forceinline__ ull dup2(float x) {
    ull r;
    asm("mov.b64 %0, {%1, %1};" : "=l"(r) : "r"(__float_as_uint(x)));
    return r;
}
__global__ void __launch_bounds__(256) k_gemm1(const float* __restrict__ A,
                                               const float* __restrict__ W,
                                               const float* __restrict__ b1) {
    __shared__ __align__(16) float As[2][BK][BM];
    __shared__ __align__(16) float Bs[2][BK][BN];
    const int tid = threadIdx.x;
    const int m0 = blockIdx.y * BM, n0 = blockIdx.x * BN;
    const int tn = tid & 31, tm = tid >> 5;
    const int ar = tid >> 2, ak = (tid & 3) << 2;
    const int br = tid >> 4, bn4 = (tid & 15) << 2;
    const int NT = DIN / BK;

    float4 aReg = *(const float4*)&A[(size_t)(m0 + ar) * DIN + ak];
    float4 bReg = *(const float4*)&W[(size_t)br * DB + n0 + bn4];
    As[0][ak + 0][ar] = aReg.x; As[0][ak + 1][ar] = aReg.y;
    As[0][ak + 2][ar] = aReg.z; As[0][ak + 3][ar] = aReg.w;
    *(float4*)&Bs[0][br][bn4] = bReg;
    __syncthreads();

    ull acc[4][2] = {};
    for (int kt = 0; kt < NT; ++kt) {
        const int cur = kt & 1;
        if (kt + 1 < NT) {
            const int kg = (kt + 1) * BK;
            aReg = *(const float4*)&A[(size_t)(m0 + ar) * DIN + kg + ak];
            bReg = *(const float4*)&W[(size_t)(kg + br) * DB + n0 + bn4];
        }
        #pragma unroll
        for (int k = 0; k < BK; ++k) {
            double2 av0 = *(const double2*)&As[cur][k][tm * 8];
            double2 av1 = *(const double2*)&As[cur][k][tm * 8 + 4];
            float2  bv  = *(const float2*)&Bs[cur][k][tn * 2];
            ull b0 = dup2(bv.x), b1d = dup2(bv.y);
            ull a0 = __double_as_longlong(av0.x), a1 = __double_as_longlong(av0.y);
            ull a2 = __double_as_longlong(av1.x), a3 = __double_as_longlong(av1.y);
            ffma2(acc[0][0], a0, b0); ffma2(acc[0][1], a0, b1d);
            ffma2(acc[1][0], a1, b0); ffma2(acc[1][1], a1, b1d);
            ffma2(acc[2][0], a2, b0); ffma2(acc[2][1], a2, b1d);
            ffma2(acc[3][0], a3, b0); ffma2(acc[3][1], a3, b1d);
        }
        if (kt + 1 < NT) {
            const int nxt = cur ^ 1;
            As[nxt][ak + 0][ar] = aReg.x; As[nxt][ak + 1][ar] = aReg.y;
            As[nxt][ak + 2][ar] = aReg.z; As[nxt][ak + 3][ar] = aReg.w;
            *(float4*)&Bs[nxt][br][bn4] = bReg;
        }
        __syncthreads();
    }
    const int n = n0 + tn * 2;
    const float bias0 = b1[n], bias1 = b1[n + 1];
    #pragma unroll
    for (int i = 0; i < 4; ++i) {
        float2 c0 = unpack2(acc[i][0]);
        float2 c1 = unpack2(acc[i][1]);
        const int m = m0 + tm * 8 + 2 * i;
        g_tf[(size_t)m * DB + n]           = fmaxf(__fadd_rn(c0.x, bias0), 0.f);
        g_tf[(size_t)m * DB + n + 1]       = fmaxf(__fadd_rn(c1.x, bias1), 0.f);
        g_tf[(size_t)(m + 1) * DB + n]     = fmaxf(__fadd_rn(c0.y, bias0), 0.f);
        g_tf[(size_t)(m + 1) * DB + n + 1] = fmaxf(__fadd_rn(c1.y, bias1), 0.f);
    }
}

/* ---- L3: fused norms (sequential scalar mul/add) + normalize ---- */
__global__ void __launch_bounds__(256) k_nq(const float* __restrict__ hist) {
    __shared__ float tile[8][32][33];
    __shared__ float nrm[256];
    const int tid = threadIdx.x;
    const int w = tid >> 5, lane = tid & 31;
    const int rbase = blockIdx.x * 256;
    {
        const int row0 = rbase + w * 32;
        const float* src = (row0 < BATCH) ? (g_tf + (size_t)row0 * DB)
                                          : (hist + (size_t)(row0 - BATCH) * DB);
        float acc = 0.f;
        for (int ch = 0; ch < 8; ++ch) {
            #pragma unroll 8
            for (int r = 0; r < 32; ++r)
                tile[w][r][lane] = src[(size_t)r * DB + ch * 32 + lane];
            __syncwarp();
            #pragma unroll 8
            for (int j = 0; j < 32; ++j) {
                float v = tile[w][lane][j];
                acc = __fadd_rn(acc, __fmul_rn(v, v));
            }
            __syncwarp();
        }
        nrm[w * 32 + lane] = __fadd_rn(__fsqrt_rn(acc), 1e-12f);
    }
    __syncthreads();
    const int q = (tid & 63) << 2;
    #pragma unroll 4
    for (int i = 0; i < 64; ++i) {
        const int row = (tid >> 6) + i * 4;
        const int gr = rbase + row;
        const float* src = (gr < BATCH) ? (g_tf + (size_t)gr * DB)
                                        : (hist + (size_t)(gr - BATCH) * DB);
        float4 v = *(const float4*)(src + q);
        const float den = nrm[row];
        float4 o;
        o.x = __fdiv_rn(v.x, den); o.y = __fdiv_rn(v.y, den);
        o.z = __fdiv_rn(v.z, den); o.w = __fdiv_rn(v.w, den);
        *(float4*)(g_bns + (size_t)gr * DB + q) = o;
    }
}

/* ---- L4: g_dT[col][b] = fl(1 - bns.bns^T); zero-MOV FFMA2, occ 2 ----
   acc packs (n,n+1); A pre-duplicated in smem so all operands arrive as
   register pairs via LDS.128. One FFMA2 per (m,n,k), ascending k. */
#define DM 128
#define DN 128
#define DK 16
__global__ void __launch_bounds__(256, 2) k_dist() {
    __shared__ __align__(16) float AsD[2][DK][2 * DM];  /* duplicated A: 32KB */
    __shared__ __align__(16) float Bs[2][DK][DN];       /* 16KB */
    const int tid = threadIdx.x;
    const int m0 = blockIdx.y * DM, n0 = blockIdx.x * DN;
    const int tn = tid & 15, tm = tid >> 4;
    const int lr = tid >> 1, lk = (tid & 1) << 3;
    const int NT = DB / DK;

    const float* Aq = g_bns + (size_t)(m0 + lr) * DB + lk;
    const float* Bq = g_bns + (size_t)(n0 + lr) * DB + lk;

    float4 a0 = *(const float4*)Aq, a1 = *(const float4*)(Aq + 4);
    float4 b0 = *(const float4*)Bq, b1 = *(const float4*)(Bq + 4);
    #pragma unroll
    for (int j = 0; j < 4; ++j) {
        float va = ((const float*)&a0)[j], vb = ((const float*)&a1)[j];
        *(float2*)&AsD[0][lk + j][2 * lr]     = make_float2(va, va);
        *(float2*)&AsD[0][lk + 4 + j][2 * lr] = make_float2(vb, vb);
        Bs[0][lk + j][lr]     = ((const float*)&b0)[j];
        Bs[0][lk + 4 + j][lr] = ((const float*)&b1)[j];
    }
    __syncthreads();

    ull acc[8][4] = {};
    for (int kt = 0; kt < NT; ++kt) {
        const int cur = kt & 1;
        if (kt + 1 < NT) {
            const int kg = (kt + 1) * DK;
            a0 = *(const float4*)(Aq + kg); a1 = *(const float4*)(Aq + kg + 4);
            b0 = *(const float4*)(Bq + kg); b1 = *(const float4*)(Bq + kg + 4);
        }
        #pragma unroll
        for (int k = 0; k < DK; ++k) {
            const float* ap = &AsD[cur][k][tm * 16];
            double2 aA = *(const double2*)ap;
            double2 aB = *(const double2*)(ap + 4);
            double2 aC = *(const double2*)(ap + 8);
            double2 aD = *(const double2*)(ap + 12);
            const float* bp = &Bs[cur][k][tn * 8];
            double2 bv = *(const double2*)bp;
            double2 bw = *(const double2*)(bp + 4);
            ull am0 = __double_as_longlong(aA.x), am1 = __double_as_longlong(aA.y);
            ull am2 = __double_as_longlong(aB.x), am3 = __double_as_longlong(aB.y);
            ull am4 = __double_as_longlong(aC.x), am5 = __double_as_longlong(aC.y);
            ull am6 = __double_as_longlong(aD.x), am7 = __double_as_longlong(aD.y);
            ull bp0 = __double_as_longlong(bv.x), bp1 = __double_as_longlong(bv.y);
            ull bp2 = __double_as_longlong(bw.x), bp3 = __double_as_longlong(bw.y);
            ffma2(acc[0][0], am0, bp0); ffma2(acc[0][1], am0, bp1);
            ffma2(acc[0][2], am0, bp2); ffma2(acc[0][3], am0, bp3);
            ffma2(acc[1][0], am1, bp0); ffma2(acc[1][1], am1, bp1);
            ffma2(acc[1][2], am1, bp2); ffma2(acc[1][3], am1, bp3);
            ffma2(acc[2][0], am2, bp0); ffma2(acc[2][1], am2, bp1);
            ffma2(acc[2][2], am2, bp2); ffma2(acc[2][3], am2, bp3);
            ffma2(acc[3][0], am3, bp0); ffma2(acc[3][1], am3, bp1);
            ffma2(acc[3][2], am3, bp2); ffma2(acc[3][3], am3, bp3);
            ffma2(acc[4][0], am4, bp0); ffma2(acc[4][1], am4, bp1);
            ffma2(acc[4][2], am4, bp2); ffma2(acc[4][3], am4, bp3);
            ffma2(acc[5][0], am5, bp0); ffma2(acc[5][1], am5, bp1);
            ffma2(acc[5][2], am5, bp2); ffma2(acc[5][3], am5, bp3);
            ffma2(acc[6][0], am6, bp0); ffma2(acc[6][1], am6, bp1);
            ffma2(acc[6][2], am6, bp2); ffma2(acc[6][3], am6, bp3);
            ffma2(acc[7][0], am7, bp0); ffma2(acc[7][1], am7, bp1);
            ffma2(acc[7][2], am7, bp2); ffma2(acc[7][3], am7, bp3);
        }
        if (kt + 1 < NT) {
            const int nxt = cur ^ 1;
            #pragma unroll
            for (int j = 0; j < 4; ++j) {
                float va = ((const float*)&a0)[j], vb = ((const float*)&a1)[j];
                *(float2*)&AsD[nxt][lk + j][2 * lr]     = make_float2(va, va);
                *(float2*)&AsD[nxt][lk + 4 + j][2 * lr] = make_float2(vb, vb);
                Bs[nxt][lk + j][lr]     = ((const float*)&b0)[j];
                Bs[nxt][lk + 4 + j][lr] = ((const float*)&b1)[j];
            }
        }
        __syncthreads();
    }
    #pragma unroll
    for (int np = 0; np < 4; ++np) {
        float c0[8], c1[8];
        #pragma unroll
        for (int i = 0; i < 8; ++i) {
            float2 v = unpack2(acc[i][np]);
            c0[i] = __fadd_rn(1.0f, -v.x);
            c1[i] = __fadd_rn(1.0f, -v.y);
        }
        const int n = n0 + tn * 8 + 2 * np;
        const size_t base = (size_t)n * BATCH + m0 + tm * 8;
        *(float4*)&g_dT[base]             = make_float4(c0[0], c0[1], c0[2], c0[3]);
        *(float4*)&g_dT[base + 4]         = make_float4(c0[4], c0[5], c0[6], c0[7]);
        *(float4*)&g_dT[base + BATCH]     = make_float4(c1[0], c1[1], c1[2], c1[3]);
        *(float4*)&g_dT[base + BATCH + 4] = make_float4(c1[4], c1[5], c1[6], c1[7]);
    }
}

/* ---- L5-7: stable counting sort of bank labels -> g_idx, g_cofs ---- */
__global__ void k_phist(const int* __restrict__ cl, const int* __restrict__ hl) {
    __shared__ int h[NC];
    const int tid = threadIdx.x;
    if (tid < NC) h[tid] = 0;
    __syncthreads();
    atomicAdd(&h[bank_lab(cl, hl, blockIdx.x * 256 + tid)], 1);
    __syncthreads();
    if (tid < NC) g_bh[blockIdx.x * NC + tid] = h[tid];
}

__global__ void k_pscan() {
    __shared__ int stot[NC];
    const int tid = threadIdx.x;
    if (tid < NC) {
        int t = 0;
        for (int b = 0; b < 256; ++b) t += g_bh[b * NC + tid];
        stot[tid] = t;
    }
    __syncthreads();
    if (tid == 0) {
        int run = 0;
        for (int c = 0; c < NC; ++c) { g_cofs[c] = run; run += stot[c]; }
        g_cofs[NC] = run;
    }
    __syncthreads();
    if (tid < NC) {
        int run = g_cofs[tid];
        for (int b = 0; b < 256; ++b) {
            g_base[b * NC + tid] = run;
            run += g_bh[b * NC + tid];
        }
    }
}

__global__ void k_pplace(const int* __restrict__ cl, const int* __restrict__ hl) {
    __shared__ int lab[256];
    const int tid = threadIdx.x;
    const int b0 = blockIdx.x * 256;
    lab[tid] = bank_lab(cl, hl, b0 + tid);
    __syncthreads();
    if (tid < NC) {
        int run = g_base[blockIdx.x * NC + tid];
        for (int j = 0; j < 256; ++j)
            if (lab[j] == tid) g_idx[run++] = b0 + j;
    }
}

/* ---- L8: fold: warp=(class, 32-b group); ascending original order ---- */
__global__ void __launch_bounds__(256) k_fold() {
    const int wg = blockIdx.x * 8 + (threadIdx.x >> 5);
    const int lane = threadIdx.x & 31;
    const int c = wg >> 6;
    const int bg = wg & 63;
    if (c >= NC) return;
    const int b = bg * 32 + lane;
    const int lo = g_cofs[c], hi = g_cofs[c + 1];
    float s = 0.f;
    int j = lo;
    for (; j + 4 <= hi; j += 4) {
        int i0 = g_idx[j], i1 = g_idx[j + 1], i2 = g_idx[j + 2], i3 = g_idx[j + 3];
        float v0 = g_dT[(size_t)i0 * BATCH + b];
        float v1 = g_dT[(size_t)i1 * BATCH + b];
        float v2 = g_dT[(size_t)i2 * BATCH + b];
        float v3 = g_dT[(size_t)i3 * BATCH + b];
        s = __fadd_rn(s, v0); s = __fadd_rn(s, v1);
        s = __fadd_rn(s, v2); s = __fadd_rn(s, v3);
    }
    for (; j < hi; ++j) s = __fadd_rn(s, g_dT[(size_t)g_idx[j] * BATCH + b]);
    g_dist[b * 32 + c] = (hi > lo) ? __fdiv_rn(s, (float)(hi - lo))
                                   : __int_as_float(0x7f800000);
}

/* ---- L9: argmin over classes ---- */
__global__ void __launch_bounds__(256) k_amin(float* __restrict__ out) {
    const int w = threadIdx.x >> 5, lane = threadIdx.x & 31;
    const int b = blockIdx.x * 8 + w;
    float dist = (lane < NC) ? g_dist[b * 32 + lane] : __int_as_float(0x7f800000);
    int idx = lane;
    #pragma unroll
    for (int off = 16; off; off >>= 1) {
        float ov = __shfl_xor_sync(0xffffffffu, dist, off);
        int oi = __shfl_xor_sync(0xffffffffu, idx, off);
        if (ov < dist || (ov == dist && oi < idx)) { dist = ov; idx = oi; }
    }
    if (lane == 0) {
        g_ltar[b] = idx;
        out[BATCH + b] = (float)idx;
    }
}

/* ---- L10: logits, argmax, per-row loss ---- */
__global__ void __launch_bounds__(256) k_logits(const float* __restrict__ Wc,
                                                const float* __restrict__ bc,
                                                float* __restrict__ out) {
    __shared__ float Ws[DB * 32];
    __shared__ float bcs[32];
    __shared__ float qrow[8][DB];
    const int tid = threadIdx.x;
    for (int i = tid; i < DB * 32; i += 256) {
        int d = i >> 5, c = i & 31;
        Ws[i] = (c < NC) ? Wc[d * NC + c] : 0.f;
    }
    if (tid < 32) bcs[tid] = (tid < NC) ? bc[tid] : 0.f;
    __syncthreads();
    const int w = tid >> 5, lane = tid & 31;
    const int b = blockIdx.x * 8 + w;
    *(float4*)&qrow[w][lane * 8]     = *(const float4*)(g_tf + (size_t)b * DB + lane * 8);
    *(float4*)&qrow[w][lane * 8 + 4] = *(const float4*)(g_tf + (size_t)b * DB + lane * 8 + 4);
    __syncwarp();
    float acc = 0.f;
    #pragma unroll 8
    for (int d = 0; d < DB; ++d) acc = __fmaf_rn(qrow[w][d], Ws[d * 32 + lane], acc);
    float logit = (lane < NC) ? __fadd_rn(acc, bcs[lane]) : -__int_as_float(0x7f800000);
    float v = logit;
    int idx = lane;
    #pragma unroll
    for (int off = 16; off; off >>= 1) {
        float ov = __shfl_xor_sync(0xffffffffu, v, off);
        int oi = __shfl_xor_sync(0xffffffffu, idx, off);
        if (ov > v || (ov == v && oi < idx)) { v = ov; idx = oi; }
    }
    const float m = v;
    float e = (lane < NC) ? expf(logit - m) : 0.f;
    #pragma unroll
    for (int off = 16; off; off >>= 1) e += __shfl_xor_sync(0xffffffffu, e, off);
    const int ltar = g_ltar[b];
    const float lt = __shfl_sync(0xffffffffu, logit, ltar);
    if (lane == 0) {
        out[b] = (float)idx;
        g_loss[b] = (logf(e) + m) - lt;
    }
}

__global__ void __launch_bounds__(256) k_final(float* __restrict__ out) {
    __shared__ float red[256];
    const int tid = threadIdx.x;
    float s = 0.f;
    for (int i = tid; i < BATCH; i += 256) s += g_loss[i];
    red[tid] = s;
    __syncthreads();
    for (int st = 128; st; st >>= 1) {
        if (tid < st) red[tid] += red[tid + st];
        __syncthreads();
    }
    if (tid == 0) out[2 * BATCH] = red[0] / (float)BATCH;
}

extern "C" void kernel_launch(void* const* d_in, const int* in_sizes, int n_in,
                              void* d_out, int out_size) {
    const float* target  = (const float*)d_in[0];
    const int*   curlab  = (const int*)d_in[1];
    const float* hist    = (const float*)d_in[2];
    const int*   histlab = (const int*)d_in[3];
    const float* W1      = (const float*)d_in[4];
    const float* b1      = (const float*)d_in[5];
    const float* Wc      = (const float*)d_in[6];
    const float* bc      = (const float*)d_in[7];
    float* out = (float*)d_out;

    k_init<<<1, 32>>>(curlab);                          /* 1 */
    dim3 g1(DB / BN, BATCH / BM);
    k_gemm1<<<g1, 256>>>(target, W1, b1);               /* 2 */
    k_nq<<<NBANK / 256, 256>>>(hist);                   /* 3 */
    dim3 gd(NBANK / DN, BATCH / DM);
    k_dist<<<gd, 256>>>();                              /* 4 <- ncu capture slot */
    k_phist<<<NBANK / 256, 256>>>(curlab, histlab);     /* 5 */
    k_pscan<<<1, 32>>>();                               /* 6 */
    k_pplace<<<NBANK / 256, 256>>>(curlab, histlab);    /* 7 */
    k_fold<<<(NC * 64 + 7) / 8, 256>>>();               /* 8 */
    k_amin<<<BATCH / 8, 256>>>(out);                    /* 9 */
    k_logits<<<BATCH / 8, 256>>>(Wc, bc, out);          /* 10 */
    k_final<<<1, 256>>>(out);                           /* 11 */
}

// round 10
// speedup vs baseline: 1.2145x; 1.2145x over previous
#include <cuda_runtime.h>
#include <math.h>

#define BATCH  2048
#define DIN    2048
#define DB     256
#define NHIST  63488
#define NBANK  (BATCH + NHIST)
#define NC     31

typedef unsigned long long ull;

__device__ float g_tf[BATCH * DB];
__device__ float g_bns[(size_t)NBANK * DB];    /* normalized bank rows (unsorted) */
__device__ float g_dT[(size_t)NBANK * BATCH];  /* 512MB: fl(1-dot), [col][b] */
__device__ float g_dist[BATCH * 32];
__device__ int   g_idx[NBANK];                 /* class-sorted -> original row */
__device__ int   g_cofs[NC + 1];
__device__ int   g_bh[256 * NC];
__device__ int   g_base[256 * NC];
__device__ int   g_ltar[BATCH];
__device__ float g_loss[BATCH];
__device__ int   g_lab64;

__device__ __forceinline__ int get_lab(const int* p, int i) {
    return g_lab64 ? p[2 * i] : p[i];
}
__device__ __forceinline__ int bank_lab(const int* cl, const int* hl, int i) {
    return (i < BATCH) ? get_lab(cl, i) : get_lab(hl, i - BATCH);
}
__device__ __forceinline__ void ffma2(ull& d, ull a, ull b) {
    asm("fma.rn.f32x2 %0, %1, %2, %0;" : "+l"(d) : "l"(a), "l"(b));
}
__device__ __forceinline__ ull dup2(float x) {
    ull r;
    asm("mov.b64 %0, {%1, %1};" : "=l"(r) : "r"(__float_as_uint(x)));
    return r;
}
__device__ __forceinline__ float2 unpack2(ull v) {
    float2 f;
    asm("mov.b64 {%0, %1}, %2;" : "=f"(f.x), "=f"(f.y) : "l"(v));
    return f;
}

/* ---- L1: label dtype detect ---- */
__global__ void k_init(const int* __restrict__ curlab) {
    if (threadIdx.x == 0) {
        int z = 1;
        for (int i = 1; i < 32; i += 2)
            if (curlab[i] != 0) z = 0;
        g_lab64 = z;
    }
}

/* ---- L2: tf = relu(target@W1+b1), sequential-k FMA chains ---- */
#define BM 64
#define BN 64
#define BK 16
__global__ void __launch_bounds__(256) k_gemm1(const float* __restrict__ A,
                                               const float* __restrict__ W,
                                               const float* __restrict__ b1) {
    __shared__ __align__(16) float As[2][BK][BM];
    __shared__ __align__(16) float Bs[2][BK][BN];
    const int tid = threadIdx.x;
    const int m0 = blockIdx.y * BM, n0 = blockIdx.x * BN;
    const int tn = tid & 31, tm = tid >> 5;
    const int ar = tid >> 2, ak = (tid & 3) << 2;
    const int br = tid >> 4, bn4 = (tid & 15) << 2;
    const int NT = DIN / BK;

    float4 aReg = *(const float4*)&A[(size_t)(m0 + ar) * DIN + ak];
    float4 bReg = *(const float4*)&W[(size_t)br * DB + n0 + bn4];
    As[0][ak + 0][ar] = aReg.x; As[0][ak + 1][ar] = aReg.y;
    As[0][ak + 2][ar] = aReg.z; As[0][ak + 3][ar] = aReg.w;
    *(float4*)&Bs[0][br][bn4] = bReg;
    __syncthreads();

    ull acc[4][2] = {};
    for (int kt = 0; kt < NT; ++kt) {
        const int cur = kt & 1;
        if (kt + 1 < NT) {
            const int kg = (kt + 1) * BK;
            aReg = *(const float4*)&A[(size_t)(m0 + ar) * DIN + kg + ak];
            bReg = *(const float4*)&W[(size_t)(kg + br) * DB + n0 + bn4];
        }
        #pragma unroll
        for (int k = 0; k < BK; ++k) {
            double2 av0 = *(const double2*)&As[cur][k][tm * 8];
            double2 av1 = *(const double2*)&As[cur][k][tm * 8 + 4];
            float2  bv  = *(const float2*)&Bs[cur][k][tn * 2];
            ull b0 = dup2(bv.x), b1d = dup2(bv.y);
            ull a0 = __double_as_longlong(av0.x), a1 = __double_as_longlong(av0.y);
            ull a2 = __double_as_longlong(av1.x), a3 = __double_as_longlong(av1.y);
            ffma2(acc[0][0], a0, b0); ffma2(acc[0][1], a0, b1d);
            ffma2(acc[1][0], a1, b0); ffma2(acc[1][1], a1, b1d);
            ffma2(acc[2][0], a2, b0); ffma2(acc[2][1], a2, b1d);
            ffma2(acc[3][0], a3, b0); ffma2(acc[3][1], a3, b1d);
        }
        if (kt + 1 < NT) {
            const int nxt = cur ^ 1;
            As[nxt][ak + 0][ar] = aReg.x; As[nxt][ak + 1][ar] = aReg.y;
            As[nxt][ak + 2][ar] = aReg.z; As[nxt][ak + 3][ar] = aReg.w;
            *(float4*)&Bs[nxt][br][bn4] = bReg;
        }
        __syncthreads();
    }
    const int n = n0 + tn * 2;
    const float bias0 = b1[n], bias1 = b1[n + 1];
    #pragma unroll
    for (int i = 0; i < 4; ++i) {
        float2 c0 = unpack2(acc[i][0]);
        float2 c1 = unpack2(acc[i][1]);
        const int m = m0 + tm * 8 + 2 * i;
        g_tf[(size_t)m * DB + n]           = fmaxf(__fadd_rn(c0.x, bias0), 0.f);
        g_tf[(size_t)m * DB + n + 1]       = fmaxf(__fadd_rn(c1.x, bias1), 0.f);
        g_tf[(size_t)(m + 1) * DB + n]     = fmaxf(__fadd_rn(c0.y, bias0), 0.f);
        g_tf[(size_t)(m + 1) * DB + n + 1] = fmaxf(__fadd_rn(c1.y, bias1), 0.f);
    }
}

/* ---- L3: fused norms (sequential scalar mul/add) + normalize ---- */
__global__ void __launch_bounds__(256) k_nq(const float* __restrict__ hist) {
    __shared__ float tile[8][32][33];
    __shared__ float nrm[256];
    const int tid = threadIdx.x;
    const int w = tid >> 5, lane = tid & 31;
    const int rbase = blockIdx.x * 256;
    {
        const int row0 = rbase + w * 32;
        const float* src = (row0 < BATCH) ? (g_tf + (size_t)row0 * DB)
                                          : (hist + (size_t)(row0 - BATCH) * DB);
        float acc = 0.f;
        for (int ch = 0; ch < 8; ++ch) {
            #pragma unroll 8
            for (int r = 0; r < 32; ++r)
                tile[w][r][lane] = src[(size_t)r * DB + ch * 32 + lane];
            __syncwarp();
            #pragma unroll 8
            for (int j = 0; j < 32; ++j) {
                float v = tile[w][lane][j];
                acc = __fadd_rn(acc, __fmul_rn(v, v));
            }
            __syncwarp();
        }
        nrm[w * 32 + lane] = __fadd_rn(__fsqrt_rn(acc), 1e-12f);
    }
    __syncthreads();
    const int q = (tid & 63) << 2;
    #pragma unroll 4
    for (int i = 0; i < 64; ++i) {
        const int row = (tid >> 6) + i * 4;
        const int gr = rbase + row;
        const float* src = (gr < BATCH) ? (g_tf + (size_t)gr * DB)
                                        : (hist + (size_t)(gr - BATCH) * DB);
        float4 v = *(const float4*)(src + q);
        const float den = nrm[row];
        float4 o;
        o.x = __fdiv_rn(v.x, den); o.y = __fdiv_rn(v.y, den);
        o.z = __fdiv_rn(v.z, den); o.w = __fdiv_rn(v.w, den);
        *(float4*)(g_bns + (size_t)gr * DB + q) = o;
    }
}

/* ---- L4: g_dT[col][b] = fl(1 - bns.bns^T)
   128x128x16 tile, 128 threads, thread tile 16m x 8n.
   acc packs (m,m+1) pairs straight from transposed As via LDS.128 (no MOVs);
   only B scalars are duplicated (8 dup2/k). 64 FFMA2 per 96 smem-bytes per k
   = 1.5 B/FFMA2 < 2.0 crossbar capacity -> FMA-pipe-bound.
   One FFMA2 per (m,n,k), ascending k => bit-exact chains unchanged. */
#define DM 128
#define DN 128
#define DK 16
__global__ void __launch_bounds__(128, 2) k_dist() {
    __shared__ __align__(16) float As[2][DK][DM];  /* 16KB, transposed [k][m] */
    __shared__ __align__(16) float Bs[2][DK][DN];  /* 16KB, [k][n] */
    const int tid = threadIdx.x;                   /* 0..127 */
    const int m0 = blockIdx.y * DM, n0 = blockIdx.x * DN;
    const int tn = tid & 15;                       /* 8 n each */
    const int tm = tid >> 4;                       /* 0..7: 16 m each */
    const int NT = DB / DK;                        /* 16 */

    const float* Aq = g_bns + (size_t)(m0 + tid) * DB;
    const float* Bq = g_bns + (size_t)(n0 + tid) * DB;

    float4 pa[4], pb[4];
    #pragma unroll
    for (int j = 0; j < 4; ++j) {
        pa[j] = *(const float4*)(Aq + 4 * j);
        pb[j] = *(const float4*)(Bq + 4 * j);
    }
    #pragma unroll
    for (int j = 0; j < 16; ++j) {
        As[0][j][tid] = ((const float*)pa)[j];
        Bs[0][j][tid] = ((const float*)pb)[j];
    }
    __syncthreads();

    ull acc[8][8] = {};  /* [m-pair][n] */
    for (int kt = 0; kt < NT; ++kt) {
        const int cur = kt & 1;
        if (kt + 1 < NT) {
            const int kg = (kt + 1) * DK;
            #pragma unroll
            for (int j = 0; j < 4; ++j) {
                pa[j] = *(const float4*)(Aq + kg + 4 * j);
                pb[j] = *(const float4*)(Bq + kg + 4 * j);
            }
        }
        #pragma unroll
        for (int k = 0; k < DK; ++k) {
            const float* ap = &As[cur][k][tm * 16];
            double2 aA = *(const double2*)ap;
            double2 aB = *(const double2*)(ap + 4);
            double2 aC = *(const double2*)(ap + 8);
            double2 aD = *(const double2*)(ap + 12);
            ull am[8];
            am[0] = __double_as_longlong(aA.x); am[1] = __double_as_longlong(aA.y);
            am[2] = __double_as_longlong(aB.x); am[3] = __double_as_longlong(aB.y);
            am[4] = __double_as_longlong(aC.x); am[5] = __double_as_longlong(aC.y);
            am[6] = __double_as_longlong(aD.x); am[7] = __double_as_longlong(aD.y);
            const float* bp = &Bs[cur][k][tn * 8];
            #pragma unroll
            for (int h = 0; h < 2; ++h) {
                float4 bv = *(const float4*)(bp + 4 * h);
                ull bb0 = dup2(bv.x), bb1 = dup2(bv.y);
                ull bb2 = dup2(bv.z), bb3 = dup2(bv.w);
                #pragma unroll
                for (int mp = 0; mp < 8; ++mp) {
                    ffma2(acc[mp][4 * h + 0], am[mp], bb0);
                    ffma2(acc[mp][4 * h + 1], am[mp], bb1);
                    ffma2(acc[mp][4 * h + 2], am[mp], bb2);
                    ffma2(acc[mp][4 * h + 3], am[mp], bb3);
                }
            }
        }
        if (kt + 1 < NT) {
            const int nxt = cur ^ 1;
            #pragma unroll
            for (int j = 0; j < 16; ++j) {
                As[nxt][j][tid] = ((const float*)pa)[j];
                Bs[nxt][j][tid] = ((const float*)pb)[j];
            }
        }
        __syncthreads();
    }

    /* transposed epilogue: per n, 16 contiguous m floats -> 4 STG.128 */
    #pragma unroll
    for (int nn = 0; nn < 8; ++nn) {
        float r[16];
        #pragma unroll
        for (int mp = 0; mp < 8; ++mp) {
            float2 v = unpack2(acc[mp][nn]);
            r[2 * mp]     = __fadd_rn(1.0f, -v.x);
            r[2 * mp + 1] = __fadd_rn(1.0f, -v.y);
        }
        const size_t base = (size_t)(n0 + tn * 8 + nn) * BATCH + m0 + tm * 16;
        *(float4*)&g_dT[base]      = make_float4(r[0],  r[1],  r[2],  r[3]);
        *(float4*)&g_dT[base + 4]  = make_float4(r[4],  r[5],  r[6],  r[7]);
        *(float4*)&g_dT[base + 8]  = make_float4(r[8],  r[9],  r[10], r[11]);
        *(float4*)&g_dT[base + 12] = make_float4(r[12], r[13], r[14], r[15]);
    }
}

/* ---- L5-7: stable counting sort of bank labels -> g_idx, g_cofs ---- */
__global__ void k_phist(const int* __restrict__ cl, const int* __restrict__ hl) {
    __shared__ int h[NC];
    const int tid = threadIdx.x;
    if (tid < NC) h[tid] = 0;
    __syncthreads();
    atomicAdd(&h[bank_lab(cl, hl, blockIdx.x * 256 + tid)], 1);
    __syncthreads();
    if (tid < NC) g_bh[blockIdx.x * NC + tid] = h[tid];
}

__global__ void k_pscan() {
    __shared__ int stot[NC];
    const int tid = threadIdx.x;
    if (tid < NC) {
        int t = 0;
        for (int b = 0; b < 256; ++b) t += g_bh[b * NC + tid];
        stot[tid] = t;
    }
    __syncthreads();
    if (tid == 0) {
        int run = 0;
        for (int c = 0; c < NC; ++c) { g_cofs[c] = run; run += stot[c]; }
        g_cofs[NC] = run;
    }
    __syncthreads();
    if (tid < NC) {
        int run = g_cofs[tid];
        for (int b = 0; b < 256; ++b) {
            g_base[b * NC + tid] = run;
            run += g_bh[b * NC + tid];
        }
    }
}

__global__ void k_pplace(const int* __restrict__ cl, const int* __restrict__ hl) {
    __shared__ int lab[256];
    const int tid = threadIdx.x;
    const int b0 = blockIdx.x * 256;
    lab[tid] = bank_lab(cl, hl, b0 + tid);
    __syncthreads();
    if (tid < NC) {
        int run = g_base[blockIdx.x * NC + tid];
        for (int j = 0; j < 256; ++j)
            if (lab[j] == tid) g_idx[run++] = b0 + j;
    }
}

/* ---- L8: fold: warp=(class, 32-b group); ascending original order ---- */
__global__ void __launch_bounds__(256) k_fold() {
    const int wg = blockIdx.x * 8 + (threadIdx.x >> 5);
    const int lane = threadIdx.x & 31;
    const int c = wg >> 6;
    const int bg = wg & 63;
    if (c >= NC) return;
    const int b = bg * 32 + lane;
    const int lo = g_cofs[c], hi = g_cofs[c + 1];
    float s = 0.f;
    int j = lo;
    for (; j + 4 <= hi; j += 4) {
        int i0 = g_idx[j], i1 = g_idx[j + 1], i2 = g_idx[j + 2], i3 = g_idx[j + 3];
        float v0 = g_dT[(size_t)i0 * BATCH + b];
        float v1 = g_dT[(size_t)i1 * BATCH + b];
        float v2 = g_dT[(size_t)i2 * BATCH + b];
        float v3 = g_dT[(size_t)i3 * BATCH + b];
        s = __fadd_rn(s, v0); s = __fadd_rn(s, v1);
        s = __fadd_rn(s, v2); s = __fadd_rn(s, v3);
    }
    for (; j < hi; ++j) s = __fadd_rn(s, g_dT[(size_t)g_idx[j] * BATCH + b]);
    g_dist[b * 32 + c] = (hi > lo) ? __fdiv_rn(s, (float)(hi - lo))
                                   : __int_as_float(0x7f800000);
}

/* ---- L9: argmin over classes ---- */
__global__ void __launch_bounds__(256) k_amin(float* __restrict__ out) {
    const int w = threadIdx.x >> 5, lane = threadIdx.x & 31;
    const int b = blockIdx.x * 8 + w;
    float dist = (lane < NC) ? g_dist[b * 32 + lane] : __int_as_float(0x7f800000);
    int idx = lane;
    #pragma unroll
    for (int off = 16; off; off >>= 1) {
        float ov = __shfl_xor_sync(0xffffffffu, dist, off);
        int oi = __shfl_xor_sync(0xffffffffu, idx, off);
        if (ov < dist || (ov == dist && oi < idx)) { dist = ov; idx = oi; }
    }
    if (lane == 0) {
        g_ltar[b] = idx;
        out[BATCH + b] = (float)idx;
    }
}

/* ---- L10: logits, argmax, per-row loss ---- */
__global__ void __launch_bounds__(256) k_logits(const float* __restrict__ Wc,
                                                const float* __restrict__ bc,
                                                float* __restrict__ out) {
    __shared__ float Ws[DB * 32];
    __shared__ float bcs[32];
    __shared__ float qrow[8][DB];
    const int tid = threadIdx.x;
    for (int i = tid; i < DB * 32; i += 256) {
        int d = i >> 5, c = i & 31;
        Ws[i] = (c < NC) ? Wc[d * NC + c] : 0.f;
    }
    if (tid < 32) bcs[tid] = (tid < NC) ? bc[tid] : 0.f;
    __syncthreads();
    const int w = tid >> 5, lane = tid & 31;
    const int b = blockIdx.x * 8 + w;
    *(float4*)&qrow[w][lane * 8]     = *(const float4*)(g_tf + (size_t)b * DB + lane * 8);
    *(float4*)&qrow[w][lane * 8 + 4] = *(const float4*)(g_tf + (size_t)b * DB + lane * 8 + 4);
    __syncwarp();
    float acc = 0.f;
    #pragma unroll 8
    for (int d = 0; d < DB; ++d) acc = __fmaf_rn(qrow[w][d], Ws[d * 32 + lane], acc);
    float logit = (lane < NC) ? __fadd_rn(acc, bcs[lane]) : -__int_as_float(0x7f800000);
    float v = logit;
    int idx = lane;
    #pragma unroll
    for (int off = 16; off; off >>= 1) {
        float ov = __shfl_xor_sync(0xffffffffu, v, off);
        int oi = __shfl_xor_sync(0xffffffffu, idx, off);
        if (ov > v || (ov == v && oi < idx)) { v = ov; idx = oi; }
    }
    const float m = v;
    float e = (lane < NC) ? expf(logit - m) : 0.f;
    #pragma unroll
    for (int off = 16; off; off >>= 1) e += __shfl_xor_sync(0xffffffffu, e, off);
    const int ltar = g_ltar[b];
    const float lt = __shfl_sync(0xffffffffu, logit, ltar);
    if (lane == 0) {
        out[b] = (float)idx;
        g_loss[b] = (logf(e) + m) - lt;
    }
}

__global__ void __launch_bounds__(256) k_final(float* __restrict__ out) {
    __shared__ float red[256];
    const int tid = threadIdx.x;
    float s = 0.f;
    for (int i = tid; i < BATCH; i += 256) s += g_loss[i];
    red[tid] = s;
    __syncthreads();
    for (int st = 128; st; st >>= 1) {
        if (tid < st) red[tid] += red[tid + st];
        __syncthreads();
    }
    if (tid == 0) out[2 * BATCH] = red[0] / (float)BATCH;
}

extern "C" void kernel_launch(void* const* d_in, const int* in_sizes, int n_in,
                              void* d_out, int out_size) {
    const float* target  = (const float*)d_in[0];
    const int*   curlab  = (const int*)d_in[1];
    const float* hist    = (const float*)d_in[2];
    const int*   histlab = (const int*)d_in[3];
    const float* W1      = (const float*)d_in[4];
    const float* b1      = (const float*)d_in[5];
    const float* Wc      = (const float*)d_in[6];
    const float* bc      = (const float*)d_in[7];
    float* out = (float*)d_out;

    k_init<<<1, 32>>>(curlab);                          /* 1 */
    dim3 g1(DB / BN, BATCH / BM);
    k_gemm1<<<g1, 256>>>(target, W1, b1);               /* 2 */
    k_nq<<<NBANK / 256, 256>>>(hist);                   /* 3 */
    dim3 gd(NBANK / DN, BATCH / DM);
    k_dist<<<gd, 128>>>();                              /* 4 <- ncu capture slot */
    k_phist<<<NBANK / 256, 256>>>(curlab, histlab);     /* 5 */
    k_pscan<<<1, 32>>>();                               /* 6 */
    k_pplace<<<NBANK / 256, 256>>>(curlab, histlab);    /* 7 */
    k_fold<<<(NC * 64 + 7) / 8, 256>>>();               /* 8 */
    k_amin<<<BATCH / 8, 256>>>(out);                    /* 9 */
    k_logits<<<BATCH / 8, 256>>>(Wc, bc, out);          /* 10 */
    k_final<<<1, 256>>>(out);                           /* 11 */
}

// round 11
// speedup vs baseline: 1.2154x; 1.0008x over previous
#include <cuda_runtime.h>
#include <math.h>

#define BATCH  2048
#define DIN    2048
#define DB     256
#define NHIST  63488
#define NBANK  (BATCH + NHIST)
#define NC     31

typedef unsigned long long ull;

__device__ float g_tf[BATCH * DB];
__device__ float g_bns[(size_t)NBANK * DB];    /* normalized bank rows (unsorted) */
__device__ float g_dT[(size_t)NBANK * BATCH];  /* 512MB: fl(1-dot), [col][b] */
__device__ float g_dist[BATCH * 32];
__device__ int   g_idx[NBANK];                 /* class-sorted -> original row */
__device__ int   g_cofs[NC + 1];
__device__ int   g_bh[256 * NC];
__device__ int   g_base[256 * NC];
__device__ int   g_ltar[BATCH];
__device__ float g_loss[BATCH];
__device__ int   g_lab64;

__device__ __forceinline__ int get_lab(const int* p, int i) {
    return g_lab64 ? p[2 * i] : p[i];
}
__device__ __forceinline__ int bank_lab(const int* cl, const int* hl, int i) {
    return (i < BATCH) ? get_lab(cl, i) : get_lab(hl, i - BATCH);
}
__device__ __forceinline__ void ffma2(ull& d, ull a, ull b) {
    asm("fma.rn.f32x2 %0, %1, %2, %0;" : "+l"(d) : "l"(a), "l"(b));
}
__device__ __forceinline__ ull dup2(float x) {
    ull r;
    asm("mov.b64 %0, {%1, %1};" : "=l"(r) : "r"(__float_as_uint(x)));
    return r;
}
__device__ __forceinline__ float2 unpack2(ull v) {
    float2 f;
    asm("mov.b64 {%0, %1}, %2;" : "=f"(f.x), "=f"(f.y) : "l"(v));
    return f;
}

/* ---- L1: label dtype detect ---- */
__global__ void k_init(const int* __restrict__ curlab) {
    if (threadIdx.x == 0) {
        int z = 1;
        for (int i = 1; i < 32; i += 2)
            if (curlab[i] != 0) z = 0;
        g_lab64 = z;
    }
}

/* ---- L2: tf = relu(target@W1+b1), sequential-k FMA chains ---- */
#define BM 64
#define BN 64
#define BK 16
__global__ void __launch_bounds__(256) k_gemm1(const float* __restrict__ A,
                                               const float* __restrict__ W,
                                               const float* __restrict__ b1) {
    __shared__ __align__(16) float As[2][BK][BM];
    __shared__ __align__(16) float Bs[2][BK][BN];
    const int tid = threadIdx.x;
    const int m0 = blockIdx.y * BM, n0 = blockIdx.x * BN;
    const int tn = tid & 31, tm = tid >> 5;
    const int ar = tid >> 2, ak = (tid & 3) << 2;
    const int br = tid >> 4, bn4 = (tid & 15) << 2;
    const int NT = DIN / BK;

    float4 aReg = *(const float4*)&A[(size_t)(m0 + ar) * DIN + ak];
    float4 bReg = *(const float4*)&W[(size_t)br * DB + n0 + bn4];
    As[0][ak + 0][ar] = aReg.x; As[0][ak + 1][ar] = aReg.y;
    As[0][ak + 2][ar] = aReg.z; As[0][ak + 3][ar] = aReg.w;
    *(float4*)&Bs[0][br][bn4] = bReg;
    __syncthreads();

    ull acc[4][2] = {};
    for (int kt = 0; kt < NT; ++kt) {
        const int cur = kt & 1;
        if (kt + 1 < NT) {
            const int kg = (kt + 1) * BK;
            aReg = *(const float4*)&A[(size_t)(m0 + ar) * DIN + kg + ak];
            bReg = *(const float4*)&W[(size_t)(kg + br) * DB + n0 + bn4];
        }
        #pragma unroll
        for (int k = 0; k < BK; ++k) {
            double2 av0 = *(const double2*)&As[cur][k][tm * 8];
            double2 av1 = *(const double2*)&As[cur][k][tm * 8 + 4];
            float2  bv  = *(const float2*)&Bs[cur][k][tn * 2];
            ull b0 = dup2(bv.x), b1d = dup2(bv.y);
            ull a0 = __double_as_longlong(av0.x), a1 = __double_as_longlong(av0.y);
            ull a2 = __double_as_longlong(av1.x), a3 = __double_as_longlong(av1.y);
            ffma2(acc[0][0], a0, b0); ffma2(acc[0][1], a0, b1d);
            ffma2(acc[1][0], a1, b0); ffma2(acc[1][1], a1, b1d);
            ffma2(acc[2][0], a2, b0); ffma2(acc[2][1], a2, b1d);
            ffma2(acc[3][0], a3, b0); ffma2(acc[3][1], a3, b1d);
        }
        if (kt + 1 < NT) {
            const int nxt = cur ^ 1;
            As[nxt][ak + 0][ar] = aReg.x; As[nxt][ak + 1][ar] = aReg.y;
            As[nxt][ak + 2][ar] = aReg.z; As[nxt][ak + 3][ar] = aReg.w;
            *(float4*)&Bs[nxt][br][bn4] = bReg;
        }
        __syncthreads();
    }
    const int n = n0 + tn * 2;
    const float bias0 = b1[n], bias1 = b1[n + 1];
    #pragma unroll
    for (int i = 0; i < 4; ++i) {
        float2 c0 = unpack2(acc[i][0]);
        float2 c1 = unpack2(acc[i][1]);
        const int m = m0 + tm * 8 + 2 * i;
        g_tf[(size_t)m * DB + n]           = fmaxf(__fadd_rn(c0.x, bias0), 0.f);
        g_tf[(size_t)m * DB + n + 1]       = fmaxf(__fadd_rn(c1.x, bias1), 0.f);
        g_tf[(size_t)(m + 1) * DB + n]     = fmaxf(__fadd_rn(c0.y, bias0), 0.f);
        g_tf[(size_t)(m + 1) * DB + n + 1] = fmaxf(__fadd_rn(c1.y, bias1), 0.f);
    }
}

/* ---- L3: fused norms (sequential scalar mul/add) + normalize ---- */
__global__ void __launch_bounds__(256) k_nq(const float* __restrict__ hist) {
    __shared__ float tile[8][32][33];
    __shared__ float nrm[256];
    const int tid = threadIdx.x;
    const int w = tid >> 5, lane = tid & 31;
    const int rbase = blockIdx.x * 256;
    {
        const int row0 = rbase + w * 32;
        const float* src = (row0 < BATCH) ? (g_tf + (size_t)row0 * DB)
                                          : (hist + (size_t)(row0 - BATCH) * DB);
        float acc = 0.f;
        for (int ch = 0; ch < 8; ++ch) {
            #pragma unroll 8
            for (int r = 0; r < 32; ++r)
                tile[w][r][lane] = src[(size_t)r * DB + ch * 32 + lane];
            __syncwarp();
            #pragma unroll 8
            for (int j = 0; j < 32; ++j) {
                float v = tile[w][lane][j];
                acc = __fadd_rn(acc, __fmul_rn(v, v));
            }
            __syncwarp();
        }
        nrm[w * 32 + lane] = __fadd_rn(__fsqrt_rn(acc), 1e-12f);
    }
    __syncthreads();
    const int q = (tid & 63) << 2;
    #pragma unroll 4
    for (int i = 0; i < 64; ++i) {
        const int row = (tid >> 6) + i * 4;
        const int gr = rbase + row;
        const float* src = (gr < BATCH) ? (g_tf + (size_t)gr * DB)
                                        : (hist + (size_t)(gr - BATCH) * DB);
        float4 v = *(const float4*)(src + q);
        const float den = nrm[row];
        float4 o;
        o.x = __fdiv_rn(v.x, den); o.y = __fdiv_rn(v.y, den);
        o.z = __fdiv_rn(v.z, den); o.w = __fdiv_rn(v.w, den);
        *(float4*)(g_bns + (size_t)gr * DB + q) = o;
    }
}

/* ---- L4: g_dT[col][b] = fl(1 - bns.bns^T)
   128x128x16 tile, 128 threads, thread tile 16m x 8n.
   acc packs (m,m+1) pairs straight from transposed As via LDS.128 (no MOVs);
   only B scalars are duplicated (8 dup2/k). 64 FFMA2 per 96 smem-bytes per k
   = 1.5 B/FFMA2 < 2.0 crossbar capacity -> FMA-pipe-bound.
   One FFMA2 per (m,n,k), ascending k => bit-exact chains unchanged. */
#define DM 128
#define DN 128
#define DK 16
__global__ void __launch_bounds__(128, 2) k_dist() {
    __shared__ __align__(16) float As[2][DK][DM];  /* 16KB, transposed [k][m] */
    __shared__ __align__(16) float Bs[2][DK][DN];  /* 16KB, [k][n] */
    const int tid = threadIdx.x;                   /* 0..127 */
    const int m0 = blockIdx.y * DM, n0 = blockIdx.x * DN;
    const int tn = tid & 15;                       /* 8 n each */
    const int tm = tid >> 4;                       /* 0..7: 16 m each */
    const int NT = DB / DK;                        /* 16 */

    const float* Aq = g_bns + (size_t)(m0 + tid) * DB;
    const float* Bq = g_bns + (size_t)(n0 + tid) * DB;

    float4 pa[4], pb[4];
    #pragma unroll
    for (int j = 0; j < 4; ++j) {
        pa[j] = *(const float4*)(Aq + 4 * j);
        pb[j] = *(const float4*)(Bq + 4 * j);
    }
    #pragma unroll
    for (int j = 0; j < 16; ++j) {
        As[0][j][tid] = ((const float*)pa)[j];
        Bs[0][j][tid] = ((const float*)pb)[j];
    }
    __syncthreads();

    ull acc[8][8] = {};  /* [m-pair][n] */
    for (int kt = 0; kt < NT; ++kt) {
        const int cur = kt & 1;
        if (kt + 1 < NT) {
            const int kg = (kt + 1) * DK;
            #pragma unroll
            for (int j = 0; j < 4; ++j) {
                pa[j] = *(const float4*)(Aq + kg + 4 * j);
                pb[j] = *(const float4*)(Bq + kg + 4 * j);
            }
        }
        #pragma unroll
        for (int k = 0; k < DK; ++k) {
            const float* ap = &As[cur][k][tm * 16];
            double2 aA = *(const double2*)ap;
            double2 aB = *(const double2*)(ap + 4);
            double2 aC = *(const double2*)(ap + 8);
            double2 aD = *(const double2*)(ap + 12);
            ull am[8];
            am[0] = __double_as_longlong(aA.x); am[1] = __double_as_longlong(aA.y);
            am[2] = __double_as_longlong(aB.x); am[3] = __double_as_longlong(aB.y);
            am[4] = __double_as_longlong(aC.x); am[5] = __double_as_longlong(aC.y);
            am[6] = __double_as_longlong(aD.x); am[7] = __double_as_longlong(aD.y);
            const float* bp = &Bs[cur][k][tn * 8];
            #pragma unroll
            for (int h = 0; h < 2; ++h) {
                float4 bv = *(const float4*)(bp + 4 * h);
                ull bb0 = dup2(bv.x), bb1 = dup2(bv.y);
                ull bb2 = dup2(bv.z), bb3 = dup2(bv.w);
                #pragma unroll
                for (int mp = 0; mp < 8; ++mp) {
                    ffma2(acc[mp][4 * h + 0], am[mp], bb0);
                    ffma2(acc[mp][4 * h + 1], am[mp], bb1);
                    ffma2(acc[mp][4 * h + 2], am[mp], bb2);
                    ffma2(acc[mp][4 * h + 3], am[mp], bb3);
                }
            }
        }
        if (kt + 1 < NT) {
            const int nxt = cur ^ 1;
            #pragma unroll
            for (int j = 0; j < 16; ++j) {
                As[nxt][j][tid] = ((const float*)pa)[j];
                Bs[nxt][j][tid] = ((const float*)pb)[j];
            }
        }
        __syncthreads();
    }

    /* transposed epilogue: per n, 16 contiguous m floats -> 4 STG.128 */
    #pragma unroll
    for (int nn = 0; nn < 8; ++nn) {
        float r[16];
        #pragma unroll
        for (int mp = 0; mp < 8; ++mp) {
            float2 v = unpack2(acc[mp][nn]);
            r[2 * mp]     = __fadd_rn(1.0f, -v.x);
            r[2 * mp + 1] = __fadd_rn(1.0f, -v.y);
        }
        const size_t base = (size_t)(n0 + tn * 8 + nn) * BATCH + m0 + tm * 16;
        *(float4*)&g_dT[base]      = make_float4(r[0],  r[1],  r[2],  r[3]);
        *(float4*)&g_dT[base + 4]  = make_float4(r[4],  r[5],  r[6],  r[7]);
        *(float4*)&g_dT[base + 8]  = make_float4(r[8],  r[9],  r[10], r[11]);
        *(float4*)&g_dT[base + 12] = make_float4(r[12], r[13], r[14], r[15]);
    }
}

/* ---- L5-7: stable counting sort of bank labels -> g_idx, g_cofs ---- */
__global__ void k_phist(const int* __restrict__ cl, const int* __restrict__ hl) {
    __shared__ int h[NC];
    const int tid = threadIdx.x;
    if (tid < NC) h[tid] = 0;
    __syncthreads();
    atomicAdd(&h[bank_lab(cl, hl, blockIdx.x * 256 + tid)], 1);
    __syncthreads();
    if (tid < NC) g_bh[blockIdx.x * NC + tid] = h[tid];
}

__global__ void k_pscan() {
    __shared__ int stot[NC];
    const int tid = threadIdx.x;
    if (tid < NC) {
        int t = 0;
        for (int b = 0; b < 256; ++b) t += g_bh[b * NC + tid];
        stot[tid] = t;
    }
    __syncthreads();
    if (tid == 0) {
        int run = 0;
        for (int c = 0; c < NC; ++c) { g_cofs[c] = run; run += stot[c]; }
        g_cofs[NC] = run;
    }
    __syncthreads();
    if (tid < NC) {
        int run = g_cofs[tid];
        for (int b = 0; b < 256; ++b) {
            g_base[b * NC + tid] = run;
            run += g_bh[b * NC + tid];
        }
    }
}

__global__ void k_pplace(const int* __restrict__ cl, const int* __restrict__ hl) {
    __shared__ int lab[256];
    const int tid = threadIdx.x;
    const int b0 = blockIdx.x * 256;
    lab[tid] = bank_lab(cl, hl, b0 + tid);
    __syncthreads();
    if (tid < NC) {
        int run = g_base[blockIdx.x * NC + tid];
        for (int j = 0; j < 256; ++j)
            if (lab[j] == tid) g_idx[run++] = b0 + j;
    }
}

/* ---- L8: fold: warp=(class, 32-b group); ascending original order ---- */
__global__ void __launch_bounds__(256) k_fold() {
    const int wg = blockIdx.x * 8 + (threadIdx.x >> 5);
    const int lane = threadIdx.x & 31;
    const int c = wg >> 6;
    const int bg = wg & 63;
    if (c >= NC) return;
    const int b = bg * 32 + lane;
    const int lo = g_cofs[c], hi = g_cofs[c + 1];
    float s = 0.f;
    int j = lo;
    for (; j + 4 <= hi; j += 4) {
        int i0 = g_idx[j], i1 = g_idx[j + 1], i2 = g_idx[j + 2], i3 = g_idx[j + 3];
        float v0 = g_dT[(size_t)i0 * BATCH + b];
        float v1 = g_dT[(size_t)i1 * BATCH + b];
        float v2 = g_dT[(size_t)i2 * BATCH + b];
        float v3 = g_dT[(size_t)i3 * BATCH + b];
        s = __fadd_rn(s, v0); s = __fadd_rn(s, v1);
        s = __fadd_rn(s, v2); s = __fadd_rn(s, v3);
    }
    for (; j < hi; ++j) s = __fadd_rn(s, g_dT[(size_t)g_idx[j] * BATCH + b]);
    g_dist[b * 32 + c] = (hi > lo) ? __fdiv_rn(s, (float)(hi - lo))
                                   : __int_as_float(0x7f800000);
}

/* ---- L9: argmin over classes ---- */
__global__ void __launch_bounds__(256) k_amin(float* __restrict__ out) {
    const int w = threadIdx.x >> 5, lane = threadIdx.x & 31;
    const int b = blockIdx.x * 8 + w;
    float dist = (lane < NC) ? g_dist[b * 32 + lane] : __int_as_float(0x7f800000);
    int idx = lane;
    #pragma unroll
    for (int off = 16; off; off >>= 1) {
        float ov = __shfl_xor_sync(0xffffffffu, dist, off);
        int oi = __shfl_xor_sync(0xffffffffu, idx, off);
        if (ov < dist || (ov == dist && oi < idx)) { dist = ov; idx = oi; }
    }
    if (lane == 0) {
        g_ltar[b] = idx;
        out[BATCH + b] = (float)idx;
    }
}

/* ---- L10: logits, argmax, per-row loss ---- */
__global__ void __launch_bounds__(256) k_logits(const float* __restrict__ Wc,
                                                const float* __restrict__ bc,
                                                float* __restrict__ out) {
    __shared__ float Ws[DB * 32];
    __shared__ float bcs[32];
    __shared__ float qrow[8][DB];
    const int tid = threadIdx.x;
    for (int i = tid; i < DB * 32; i += 256) {
        int d = i >> 5, c = i & 31;
        Ws[i] = (c < NC) ? Wc[d * NC + c] : 0.f;
    }
    if (tid < 32) bcs[tid] = (tid < NC) ? bc[tid] : 0.f;
    __syncthreads();
    const int w = tid >> 5, lane = tid & 31;
    const int b = blockIdx.x * 8 + w;
    *(float4*)&qrow[w][lane * 8]     = *(const float4*)(g_tf + (size_t)b * DB + lane * 8);
    *(float4*)&qrow[w][lane * 8 + 4] = *(const float4*)(g_tf + (size_t)b * DB + lane * 8 + 4);
    __syncwarp();
    float acc = 0.f;
    #pragma unroll 8
    for (int d = 0; d < DB; ++d) acc = __fmaf_rn(qrow[w][d], Ws[d * 32 + lane], acc);
    float logit = (lane < NC) ? __fadd_rn(acc, bcs[lane]) : -__int_as_float(0x7f800000);
    float v = logit;
    int idx = lane;
    #pragma unroll
    for (int off = 16; off; off >>= 1) {
        float ov = __shfl_xor_sync(0xffffffffu, v, off);
        int oi = __shfl_xor_sync(0xffffffffu, idx, off);
        if (ov > v || (ov == v && oi < idx)) { v = ov; idx = oi; }
    }
    const float m = v;
    float e = (lane < NC) ? expf(logit - m) : 0.f;
    #pragma unroll
    for (int off = 16; off; off >>= 1) e += __shfl_xor_sync(0xffffffffu, e, off);
    const int ltar = g_ltar[b];
    const float lt = __shfl_sync(0xffffffffu, logit, ltar);
    if (lane == 0) {
        out[b] = (float)idx;
        g_loss[b] = (logf(e) + m) - lt;
    }
}

__global__ void __launch_bounds__(256) k_final(float* __restrict__ out) {
    __shared__ float red[256];
    const int tid = threadIdx.x;
    float s = 0.f;
    for (int i = tid; i < BATCH; i += 256) s += g_loss[i];
    red[tid] = s;
    __syncthreads();
    for (int st = 128; st; st >>= 1) {
        if (tid < st) red[tid] += red[tid + st];
        __syncthreads();
    }
    if (tid == 0) out[2 * BATCH] = red[0] / (float)BATCH;
}

extern "C" void kernel_launch(void* const* d_in, const int* in_sizes, int n_in,
                              void* d_out, int out_size) {
    const float* target  = (const float*)d_in[0];
    const int*   curlab  = (const int*)d_in[1];
    const float* hist    = (const float*)d_in[2];
    const int*   histlab = (const int*)d_in[3];
    const float* W1      = (const float*)d_in[4];
    const float* b1      = (const float*)d_in[5];
    const float* Wc      = (const float*)d_in[6];
    const float* bc      = (const float*)d_in[7];
    float* out = (float*)d_out;

    k_init<<<1, 32>>>(curlab);                          /* 1 */
    dim3 g1(DB / BN, BATCH / BM);
    k_gemm1<<<g1, 256>>>(target, W1, b1);               /* 2 */
    k_nq<<<NBANK / 256, 256>>>(hist);                   /* 3 */
    dim3 gd(NBANK / DN, BATCH / DM);
    k_dist<<<gd, 128>>>();                              /* 4 <- ncu capture slot */
    k_phist<<<NBANK / 256, 256>>>(curlab, histlab);     /* 5 */
    k_pscan<<<1, 32>>>();                               /* 6 */
    k_pplace<<<NBANK / 256, 256>>>(curlab, histlab);    /* 7 */
    k_fold<<<(NC * 64 + 7) / 8, 256>>>();               /* 8 */
    k_amin<<<BATCH / 8, 256>>>(out);                    /* 9 */
    k_logits<<<BATCH / 8, 256>>>(Wc, bc, out);          /* 10 */
    k_final<<<1, 256>>>(out);                           /* 11 */
}

// round 12
// speedup vs baseline: 3.2508x; 2.6746x over previous
#include <cuda_runtime.h>
#include <math.h>

#define BATCH  2048
#define DIN    2048
#define DB     256
#define NHIST  63488
#define NBANK  (BATCH + NHIST)
#define NC     31
#define CHUNK  64

typedef unsigned long long ull;

__device__ float  g_tf[BATCH * DB];
__device__ float  g_qn[BATCH * DB];
__device__ float  g_norm[NBANK];
__device__ float  g_bns[(size_t)NBANK * DB];   /* class-sorted normalized bank */
__device__ double g_Gp[8 * NC * DB];
__device__ double g_Gd[NC * DB];
__device__ float  g_rex[BATCH * 32];
__device__ int    g_rowlist[NC * BATCH];
__device__ int    g_nrows[NC];
__device__ int    g_pos[NBANK];
__device__ int    g_cofs[NC + 1];
__device__ int    g_bh[256 * NC];
__device__ int    g_base[256 * NC];
__device__ int    g_ltar[BATCH];
__device__ float  g_loss[BATCH];
__device__ int    g_lab64;

__device__ __forceinline__ int get_lab(const int* p, int i) {
    return g_lab64 ? p[2 * i] : p[i];
}
__device__ __forceinline__ int bank_lab(const int* cl, const int* hl, int i) {
    return (i < BATCH) ? get_lab(cl, i) : get_lab(hl, i - BATCH);
}
__device__ __forceinline__ void ffma2(ull& d, ull a, ull b) {
    asm("fma.rn.f32x2 %0, %1, %2, %0;" : "+l"(d) : "l"(a), "l"(b));
}
__device__ __forceinline__ ull dup2(float x) {
    ull r;
    asm("mov.b64 %0, {%1, %1};" : "=l"(r) : "r"(__float_as_uint(x)));
    return r;
}
__device__ __forceinline__ float2 unpack2(ull v) {
    float2 f;
    asm("mov.b64 {%0, %1}, %2;" : "=f"(f.x), "=f"(f.y) : "l"(v));
    return f;
}

__global__ void k_init(const int* __restrict__ curlab) {
    if (threadIdx.x < NC) g_nrows[threadIdx.x] = 0;
    if (threadIdx.x == 0) {
        int z = 1;
        for (int i = 1; i < 32; i += 2)
            if (curlab[i] != 0) z = 0;
        g_lab64 = z;
    }
}

/* ---- stable counting sort -> g_pos, g_cofs (round-6 verified) ---- */
__global__ void k_phist(const int* __restrict__ cl, const int* __restrict__ hl) {
    __shared__ int h[NC];
    const int tid = threadIdx.x;
    if (tid < NC) h[tid] = 0;
    __syncthreads();
    atomicAdd(&h[bank_lab(cl, hl, blockIdx.x * 256 + tid)], 1);
    __syncthreads();
    if (tid < NC) g_bh[blockIdx.x * NC + tid] = h[tid];
}

__global__ void k_pscan() {
    __shared__ int stot[NC];
    const int tid = threadIdx.x;
    if (tid < NC) {
        int t = 0;
        for (int b = 0; b < 256; ++b) t += g_bh[b * NC + tid];
        stot[tid] = t;
    }
    __syncthreads();
    if (tid == 0) {
        int run = 0;
        for (int c = 0; c < NC; ++c) { g_cofs[c] = run; run += stot[c]; }
        g_cofs[NC] = run;
    }
    __syncthreads();
    if (tid < NC) {
        int run = g_cofs[tid];
        for (int b = 0; b < 256; ++b) {
            g_base[b * NC + tid] = run;
            run += g_bh[b * NC + tid];
        }
    }
}

__global__ void k_pplace(const int* __restrict__ cl, const int* __restrict__ hl) {
    __shared__ int lab[256];
    const int tid = threadIdx.x;
    const int b0 = blockIdx.x * 256;
    lab[tid] = bank_lab(cl, hl, b0 + tid);
    __syncthreads();
    if (tid < NC) {
        int run = g_base[blockIdx.x * NC + tid];
        for (int j = 0; j < 256; ++j)
            if (lab[j] == tid) g_pos[b0 + j] = run++;
    }
}

/* ---- tf = relu(target@W1+b1), sequential-k FMA chains (verified) ---- */
#define BM 64
#define BN 64
#define BK 16
__global__ void __launch_bounds__(256) k_gemm1(const float* __restrict__ A,
                                               const float* __restrict__ W,
                                               const float* __restrict__ b1) {
    __shared__ __align__(16) float As[2][BK][BM];
    __shared__ __align__(16) float Bs[2][BK][BN];
    const int tid = threadIdx.x;
    const int m0 = blockIdx.y * BM, n0 = blockIdx.x * BN;
    const int tn = tid & 31, tm = tid >> 5;
    const int ar = tid >> 2, ak = (tid & 3) << 2;
    const int br = tid >> 4, bn4 = (tid & 15) << 2;
    const int NT = DIN / BK;

    float4 aReg = *(const float4*)&A[(size_t)(m0 + ar) * DIN + ak];
    float4 bReg = *(const float4*)&W[(size_t)br * DB + n0 + bn4];
    As[0][ak + 0][ar] = aReg.x; As[0][ak + 1][ar] = aReg.y;
    As[0][ak + 2][ar] = aReg.z; As[0][ak + 3][ar] = aReg.w;
    *(float4*)&Bs[0][br][bn4] = bReg;
    __syncthreads();

    ull acc[4][2] = {};
    for (int kt = 0; kt < NT; ++kt) {
        const int cur = kt & 1;
        if (kt + 1 < NT) {
            const int kg = (kt + 1) * BK;
            aReg = *(const float4*)&A[(size_t)(m0 + ar) * DIN + kg + ak];
            bReg = *(const float4*)&W[(size_t)(kg + br) * DB + n0 + bn4];
        }
        #pragma unroll
        for (int k = 0; k < BK; ++k) {
            double2 av0 = *(const double2*)&As[cur][k][tm * 8];
            double2 av1 = *(const double2*)&As[cur][k][tm * 8 + 4];
            float2  bv  = *(const float2*)&Bs[cur][k][tn * 2];
            ull b0 = dup2(bv.x), b1d = dup2(bv.y);
            ull a0 = __double_as_longlong(av0.x), a1 = __double_as_longlong(av0.y);
            ull a2 = __double_as_longlong(av1.x), a3 = __double_as_longlong(av1.y);
            ffma2(acc[0][0], a0, b0); ffma2(acc[0][1], a0, b1d);
            ffma2(acc[1][0], a1, b0); ffma2(acc[1][1], a1, b1d);
            ffma2(acc[2][0], a2, b0); ffma2(acc[2][1], a2, b1d);
            ffma2(acc[3][0], a3, b0); ffma2(acc[3][1], a3, b1d);
        }
        if (kt + 1 < NT) {
            const int nxt = cur ^ 1;
            As[nxt][ak + 0][ar] = aReg.x; As[nxt][ak + 1][ar] = aReg.y;
            As[nxt][ak + 2][ar] = aReg.z; As[nxt][ak + 3][ar] = aReg.w;
            *(float4*)&Bs[nxt][br][bn4] = bReg;
        }
        __syncthreads();
    }
    const int n = n0 + tn * 2;
    const float bias0 = b1[n], bias1 = b1[n + 1];
    #pragma unroll
    for (int i = 0; i < 4; ++i) {
        float2 c0 = unpack2(acc[i][0]);
        float2 c1 = unpack2(acc[i][1]);
        const int m = m0 + tm * 8 + 2 * i;
        g_tf[(size_t)m * DB + n]           = fmaxf(__fadd_rn(c0.x, bias0), 0.f);
        g_tf[(size_t)m * DB + n + 1]       = fmaxf(__fadd_rn(c1.x, bias1), 0.f);
        g_tf[(size_t)(m + 1) * DB + n]     = fmaxf(__fadd_rn(c0.y, bias0), 0.f);
        g_tf[(size_t)(m + 1) * DB + n + 1] = fmaxf(__fadd_rn(c1.y, bias1), 0.f);
    }
}

/* ---- norms: sequential scalar, separate mul/add (verified) ---- */
__global__ void __launch_bounds__(256) k_norm(const float* __restrict__ hist) {
    __shared__ float tile[8][32][33];
    const int w = threadIdx.x >> 5, lane = threadIdx.x & 31;
    const int row0 = blockIdx.x * 256 + w * 32;
    const float* src = (row0 < BATCH) ? (g_tf + (size_t)row0 * DB)
                                      : (hist + (size_t)(row0 - BATCH) * DB);
    float acc = 0.f;
    for (int ch = 0; ch < 8; ++ch) {
        #pragma unroll 8
        for (int r = 0; r < 32; ++r)
            tile[w][r][lane] = src[(size_t)r * DB + ch * 32 + lane];
        __syncwarp();
        #pragma unroll 8
        for (int j = 0; j < 32; ++j) {
            float v = tile[w][lane][j];
            acc = __fadd_rn(acc, __fmul_rn(v, v));
        }
        __syncwarp();
    }
    g_norm[row0 + lane] = __fsqrt_rn(acc);
}

/* ---- normalize + class-sorted scatter + qn (verified) ---- */
__global__ void __launch_bounds__(256) k_qnrm(const float* __restrict__ hist) {
    const int gid = blockIdx.x * 256 + threadIdx.x;
    const int r = gid >> 6, q = (gid & 63) << 2;
    const float* src = (r < BATCH) ? (g_tf + (size_t)r * DB)
                                   : (hist + (size_t)(r - BATCH) * DB);
    float4 v = *(const float4*)(src + q);
    const float den = __fadd_rn(g_norm[r], 1e-12f);
    float4 o;
    o.x = __fdiv_rn(v.x, den); o.y = __fdiv_rn(v.y, den);
    o.z = __fdiv_rn(v.z, den); o.w = __fdiv_rn(v.w, den);
    *(float4*)(g_bns + (size_t)g_pos[r] * DB + q) = o;
    if (r < BATCH) *(float4*)(g_qn + (size_t)r * DB + q) = o;
}

/* ---- double class sums over sorted segments (order-insensitive) ---- */
__global__ void k_gsum() {   /* grid (NC, 8), block 256 */
    const int c = blockIdx.x, p = blockIdx.y, d = threadIdx.x;
    const int lo = g_cofs[c], cnt = g_cofs[c + 1] - lo;
    const int i0 = lo + (int)(((long long)cnt * p) >> 3);
    const int i1 = lo + (int)(((long long)cnt * (p + 1)) >> 3);
    double a0 = 0, a1 = 0, a2 = 0, a3 = 0;
    int i = i0;
    for (; i + 4 <= i1; i += 4) {
        a0 += (double)g_bns[(size_t)i * DB + d];
        a1 += (double)g_bns[(size_t)(i + 1) * DB + d];
        a2 += (double)g_bns[(size_t)(i + 2) * DB + d];
        a3 += (double)g_bns[(size_t)(i + 3) * DB + d];
    }
    for (; i < i1; ++i) a0 += (double)g_bns[(size_t)i * DB + d];
    g_Gp[(p * NC + c) * DB + d] = (a0 + a1) + (a2 + a3);
}

__global__ void k_gred() {   /* grid NC, block 256 */
    const int c = blockIdx.x, d = threadIdx.x;
    double s = 0;
    for (int p = 0; p < 8; ++p) s += g_Gp[(p * NC + c) * DB + d];
    g_Gd[c * DB + d] = s;
}

/* ---- screen: double means + worst-case margins -> contenders ---- */
__global__ void __launch_bounds__(256) k_screen() {  /* grid 256 */
    __shared__ float qs[8][256];
    const int w = threadIdx.x >> 5, lane = threadIdx.x & 31;
    const int b = blockIdx.x * 8 + w;
    for (int j = lane; j < 256; j += 32) qs[w][j] = g_qn[(size_t)b * DB + j];
    __syncwarp();
    double t = 1e300, Mc = 0.0;
    if (lane < NC) {
        const int lo = g_cofs[lane], cnt = g_cofs[lane + 1] - lo;
        if (cnt > 0) {
            const double* G = &g_Gd[lane * DB];
            double a0 = 0, a1 = 0, a2 = 0, a3 = 0;
            #pragma unroll 4
            for (int d = 0; d < 256; d += 4) {
                a0 += (double)qs[w][d]     * G[d];
                a1 += (double)qs[w][d + 1] * G[d + 1];
                a2 += (double)qs[w][d + 2] * G[d + 2];
                a3 += (double)qs[w][d + 3] * G[d + 3];
            }
            double dot = (a0 + a1) + (a2 + a3);
            t = ((double)cnt - dot) / (double)cnt;
            Mc = 6.05e-8 * (double)(cnt + 8) + 2.5e-5;
        }
    }
    double tmin = t, Mmin = Mc;
    #pragma unroll
    for (int off = 16; off; off >>= 1) {
        double ov = __shfl_xor_sync(0xffffffffu, tmin, off);
        double om = __shfl_xor_sync(0xffffffffu, Mmin, off);
        if (ov < tmin) { tmin = ov; Mmin = om; }
    }
    const bool cont = (lane < NC) && (t <= tmin + Mc + Mmin);
    const unsigned mask = __ballot_sync(0xffffffffu, cont);
    g_rex[b * 32 + lane] = __int_as_float(0x7f800000);
    if (__popc(mask) == 1) {
        if (lane == 0) g_ltar[b] = __ffs(mask) - 1;
    } else {
        if (lane == 0) g_ltar[b] = -1;
        if (cont) {
            int k = atomicAdd(&g_nrows[lane], 1);
            g_rowlist[lane * BATCH + k] = b;
        }
    }
}

/* ---- exact pass: bit-exact reference means for contender (b,c) ---- */
extern __shared__ float dynsm[];
__global__ void __launch_bounds__(256) k_exact() {  /* grid (NC, 256) */
    float* As = dynsm;                         /* CHUNK*257 */
    float* qs = dynsm + CHUNK * 257;           /* 8*256 */
    float* fb = qs + 8 * 256;                  /* 8*64 */
    const int c = blockIdx.x;
    const int nr = g_nrows[c];
    if ((int)(blockIdx.y * 8) >= nr) return;
    const int w = threadIdx.x >> 5, lane = threadIdx.x & 31;
    const int idx = blockIdx.y * 8 + w;
    const int lo = g_cofs[c], cnt = g_cofs[c + 1] - lo;
    const bool act = (idx < nr);
    const int b = act ? g_rowlist[c * BATCH + idx] : 0;
    for (int j = lane; j < 256; j += 32) qs[w * 256 + j] = g_qn[(size_t)b * DB + j];
    float s = 0.f;
    const int nch = (cnt + CHUNK - 1) / CHUNK;
    for (int ch = 0; ch < nch; ++ch) {
        __syncthreads();
        const int base = lo + ch * CHUNK;
        const int lim = lo + cnt;
        for (int u = threadIdx.x; u < CHUNK * 64; u += 256) {
            const int r = u >> 6, c4 = (u & 63) << 2;
            if (base + r < lim) {
                float4 v = *(const float4*)&g_bns[(size_t)(base + r) * DB + c4];
                float* dst = &As[r * 257 + c4];
                dst[0] = v.x; dst[1] = v.y; dst[2] = v.z; dst[3] = v.w;
            }
        }
        __syncthreads();
        if (act) {
            const float* q = &qs[w * 256];
            const float* r0 = &As[lane * 257];
            const float* r1 = &As[(lane + 32) * 257];
            float a0 = 0.f, a1 = 0.f;
            #pragma unroll 8
            for (int d = 0; d < 256; ++d) {
                a0 = __fmaf_rn(q[d], r0[d], a0);
                a1 = __fmaf_rn(q[d], r1[d], a1);
            }
            fb[w * 64 + lane]      = __fadd_rn(1.0f, -a0);
            fb[w * 64 + 32 + lane] = __fadd_rn(1.0f, -a1);
            __syncwarp();
            int m = cnt - ch * CHUNK;
            if (m > CHUNK) m = CHUNK;
            for (int j = 0; j < m; ++j) s = __fadd_rn(s, fb[w * 64 + j]);
        }
    }
    if (act && lane == 0) g_rex[b * 32 + c] = __fdiv_rn(s, (float)cnt);
}

/* ---- decide: single-contender fast path or exact argmin ---- */
__global__ void __launch_bounds__(256) k_decide(float* __restrict__ out) {
    const int w = threadIdx.x >> 5, lane = threadIdx.x & 31;
    const int b = blockIdx.x * 8 + w;
    int lt = g_ltar[b];
    if (lt < 0) {
        float v = (lane < NC) ? g_rex[b * 32 + lane] : __int_as_float(0x7f800000);
        int idx = lane;
        #pragma unroll
        for (int off = 16; off; off >>= 1) {
            float ov = __shfl_xor_sync(0xffffffffu, v, off);
            int oi = __shfl_xor_sync(0xffffffffu, idx, off);
            if (ov < v || (ov == v && oi < idx)) { v = ov; idx = oi; }
        }
        lt = idx;
        if (lane == 0) g_ltar[b] = lt;
    }
    if (lane == 0) out[BATCH + b] = (float)lt;
}

/* ---- logits, argmax, per-row loss (verified) ---- */
__global__ void __launch_bounds__(256) k_logits(const float* __restrict__ Wc,
                                                const float* __restrict__ bc,
                                                float* __restrict__ out) {
    __shared__ float Ws[DB * 32];
    __shared__ float bcs[32];
    __shared__ float qrow[8][DB];
    const int tid = threadIdx.x;
    for (int i = tid; i < DB * 32; i += 256) {
        int d = i >> 5, c = i & 31;
        Ws[i] = (c < NC) ? Wc[d * NC + c] : 0.f;
    }
    if (tid < 32) bcs[tid] = (tid < NC) ? bc[tid] : 0.f;
    __syncthreads();
    const int w = tid >> 5, lane = tid & 31;
    const int b = blockIdx.x * 8 + w;
    *(float4*)&qrow[w][lane * 8]     = *(const float4*)(g_tf + (size_t)b * DB + lane * 8);
    *(float4*)&qrow[w][lane * 8 + 4] = *(const float4*)(g_tf + (size_t)b * DB + lane * 8 + 4);
    __syncwarp();
    float acc = 0.f;
    #pragma unroll 8
    for (int d = 0; d < DB; ++d) acc = __fmaf_rn(qrow[w][d], Ws[d * 32 + lane], acc);
    float logit = (lane < NC) ? __fadd_rn(acc, bcs[lane]) : -__int_as_float(0x7f800000);
    float v = logit;
    int idx = lane;
    #pragma unroll
    for (int off = 16; off; off >>= 1) {
        float ov = __shfl_xor_sync(0xffffffffu, v, off);
        int oi = __shfl_xor_sync(0xffffffffu, idx, off);
        if (ov > v || (ov == v && oi < idx)) { v = ov; idx = oi; }
    }
    const float m = v;
    float e = (lane < NC) ? expf(logit - m) : 0.f;
    #pragma unroll
    for (int off = 16; off; off >>= 1) e += __shfl_xor_sync(0xffffffffu, e, off);
    const int ltar = g_ltar[b];
    const float lt = __shfl_sync(0xffffffffu, logit, ltar);
    if (lane == 0) {
        out[b] = (float)idx;
        g_loss[b] = (logf(e) + m) - lt;
    }
}

__global__ void __launch_bounds__(256) k_final(float* __restrict__ out) {
    __shared__ float red[256];
    const int tid = threadIdx.x;
    float s = 0.f;
    for (int i = tid; i < BATCH; i += 256) s += g_loss[i];
    red[tid] = s;
    __syncthreads();
    for (int st = 128; st; st >>= 1) {
        if (tid < st) red[tid] += red[tid + st];
        __syncthreads();
    }
    if (tid == 0) out[2 * BATCH] = red[0] / (float)BATCH;
}

extern "C" void kernel_launch(void* const* d_in, const int* in_sizes, int n_in,
                              void* d_out, int out_size) {
    const float* target  = (const float*)d_in[0];
    const int*   curlab  = (const int*)d_in[1];
    const float* hist    = (const float*)d_in[2];
    const int*   histlab = (const int*)d_in[3];
    const float* W1      = (const float*)d_in[4];
    const float* b1      = (const float*)d_in[5];
    const float* Wc      = (const float*)d_in[6];
    const float* bc      = (const float*)d_in[7];
    float* out = (float*)d_out;

    const int exsmem = (CHUNK * 257 + 8 * 256 + 8 * 64) * 4;  /* 76032 B */
    cudaFuncSetAttribute(k_exact, cudaFuncAttributeMaxDynamicSharedMemorySize, exsmem);

    k_init<<<1, 32>>>(curlab);
    k_phist<<<NBANK / 256, 256>>>(curlab, histlab);
    k_pscan<<<1, 32>>>();
    k_pplace<<<NBANK / 256, 256>>>(curlab, histlab);
    dim3 g1(DB / BN, BATCH / BM);
    k_gemm1<<<g1, 256>>>(target, W1, b1);
    k_norm<<<NBANK / 256, 256>>>(hist);
    k_qnrm<<<(NBANK * 64) / 256, 256>>>(hist);
    dim3 gs(NC, 8);
    k_gsum<<<gs, 256>>>();
    k_gred<<<NC, 256>>>();
    k_screen<<<BATCH / 8, 256>>>();
    dim3 ge(NC, 256);
    k_exact<<<ge, 256, exsmem>>>();
    k_decide<<<BATCH / 8, 256>>>(out);
    k_logits<<<BATCH / 8, 256>>>(Wc, bc, out);
    k_final<<<1, 256>>>(out);
}

// round 15
// speedup vs baseline: 3.2946x; 1.0135x over previous
#include <cuda_runtime.h>
#include <math.h>

#define BATCH  2048
#define DIN    2048
#define DB     256
#define NHIST  63488
#define NBANK  (BATCH + NHIST)
#define NC     31
#define CHUNK  64
#define QROWS  32
#define STR    260   /* smem row stride: float4-aligned, 260%32=4 skew */

typedef unsigned long long ull;

__device__ float  g_tf[BATCH * DB];
__device__ float  g_qn[BATCH * DB];
__device__ float  g_norm[NBANK];
__device__ float  g_rcp[NBANK];
__device__ float  g_bns[(size_t)NBANK * DB];   /* class-sorted normalized bank */
__device__ double g_Gp[8 * NC * DB];
__device__ double g_Gd[NC * DB];
__device__ float  g_rex[BATCH * 32];
__device__ int    g_rowlist[NC * BATCH];
__device__ int    g_nrows[NC];
__device__ int    g_pos[NBANK];
__device__ int    g_cofs[NC + 1];
__device__ int    g_bh[256 * NC];
__device__ int    g_base[256 * NC];
__device__ int    g_ltar[BATCH];
__device__ float  g_loss[BATCH];
__device__ int    g_lab64;

__device__ __forceinline__ int get_lab(const int* p, int i) {
    return g_lab64 ? p[2 * i] : p[i];
}
__device__ __forceinline__ int bank_lab(const int* cl, const int* hl, int i) {
    return (i < BATCH) ? get_lab(cl, i) : get_lab(hl, i - BATCH);
}
__device__ __forceinline__ void ffma2(ull& d, ull a, ull b) {
    asm("fma.rn.f32x2 %0, %1, %2, %0;" : "+l"(d) : "l"(a), "l"(b));
}
__device__ __forceinline__ ull dup2(float x) {
    ull r;
    asm("mov.b64 %0, {%1, %1};" : "=l"(r) : "r"(__float_as_uint(x)));
    return r;
}
__device__ __forceinline__ float2 unpack2(ull v) {
    float2 f;
    asm("mov.b64 {%0, %1}, %2;" : "=f"(f.x), "=f"(f.y) : "l"(v));
    return f;
}
/* Markstein: y = RN(1/d) given -> returns RN(x/d) bit-exactly */
__device__ __forceinline__ float div_ms(float x, float d, float y) {
    float q0 = __fmul_rn(x, y);
    float e  = __fmaf_rn(-d, q0, x);
    return __fmaf_rn(e, y, q0);
}

__global__ void k_init(const int* __restrict__ curlab) {
    if (threadIdx.x < NC) g_nrows[threadIdx.x] = 0;
    if (threadIdx.x == 0) {
        int z = 1;
        for (int i = 1; i < 32; i += 2)
            if (curlab[i] != 0) z = 0;
        g_lab64 = z;
    }
}

/* ---- stable counting sort -> g_pos, g_cofs (verified) ---- */
__global__ void k_phist(const int* __restrict__ cl, const int* __restrict__ hl) {
    __shared__ int h[NC];
    const int tid = threadIdx.x;
    if (tid < NC) h[tid] = 0;
    __syncthreads();
    atomicAdd(&h[bank_lab(cl, hl, blockIdx.x * 256 + tid)], 1);
    __syncthreads();
    if (tid < NC) g_bh[blockIdx.x * NC + tid] = h[tid];
}

__global__ void k_pscan() {
    __shared__ int stot[NC];
    const int tid = threadIdx.x;
    if (tid < NC) {
        int t = 0;
        for (int b = 0; b < 256; ++b) t += g_bh[b * NC + tid];
        stot[tid] = t;
    }
    __syncthreads();
    if (tid == 0) {
        int run = 0;
        for (int c = 0; c < NC; ++c) { g_cofs[c] = run; run += stot[c]; }
        g_cofs[NC] = run;
    }
    __syncthreads();
    if (tid < NC) {
        int run = g_cofs[tid];
        for (int b = 0; b < 256; ++b) {
            g_base[b * NC + tid] = run;
            run += g_bh[b * NC + tid];
        }
    }
}

__global__ void k_pplace(const int* __restrict__ cl, const int* __restrict__ hl) {
    __shared__ int lab[256];
    const int tid = threadIdx.x;
    const int b0 = blockIdx.x * 256;
    lab[tid] = bank_lab(cl, hl, b0 + tid);
    __syncthreads();
    if (tid < NC) {
        int run = g_base[blockIdx.x * NC + tid];
        for (int j = 0; j < 256; ++j)
            if (lab[j] == tid) g_pos[b0 + j] = run++;
    }
}

/* ---- tf = relu(target@W1+b1), sequential-k FMA chains (verified) ---- */
#define BM 64
#define BN 64
#define BK 16
__global__ void __launch_bounds__(256) k_gemm1(const float* __restrict__ A,
                                               const float* __restrict__ W,
                                               const float* __restrict__ b1) {
    __shared__ __align__(16) float As[2][BK][BM];
    __shared__ __align__(16) float Bs[2][BK][BN];
    const int tid = threadIdx.x;
    const int m0 = blockIdx.y * BM, n0 = blockIdx.x * BN;
    const int tn = tid & 31, tm = tid >> 5;
    const int ar = tid >> 2, ak = (tid & 3) << 2;
    const int br = tid >> 4, bn4 = (tid & 15) << 2;
    const int NT = DIN / BK;

    float4 aReg = *(const float4*)&A[(size_t)(m0 + ar) * DIN + ak];
    float4 bReg = *(const float4*)&W[(size_t)br * DB + n0 + bn4];
    As[0][ak + 0][ar] = aReg.x; As[0][ak + 1][ar] = aReg.y;
    As[0][ak + 2][ar] = aReg.z; As[0][ak + 3][ar] = aReg.w;
    *(float4*)&Bs[0][br][bn4] = bReg;
    __syncthreads();

    ull acc[4][2] = {};
    for (int kt = 0; kt < NT; ++kt) {
        const int cur = kt & 1;
        if (kt + 1 < NT) {
            const int kg = (kt + 1) * BK;
            aReg = *(const float4*)&A[(size_t)(m0 + ar) * DIN + kg + ak];
            bReg = *(const float4*)&W[(size_t)(kg + br) * DB + n0 + bn4];
        }
        #pragma unroll
        for (int k = 0; k < BK; ++k) {
            double2 av0 = *(const double2*)&As[cur][k][tm * 8];
            double2 av1 = *(const double2*)&As[cur][k][tm * 8 + 4];
            float2  bv  = *(const float2*)&Bs[cur][k][tn * 2];
            ull b0 = dup2(bv.x), b1d = dup2(bv.y);
            ull a0 = __double_as_longlong(av0.x), a1 = __double_as_longlong(av0.y);
            ull a2 = __double_as_longlong(av1.x), a3 = __double_as_longlong(av1.y);
            ffma2(acc[0][0], a0, b0); ffma2(acc[0][1], a0, b1d);
            ffma2(acc[1][0], a1, b0); ffma2(acc[1][1], a1, b1d);
            ffma2(acc[2][0], a2, b0); ffma2(acc[2][1], a2, b1d);
            ffma2(acc[3][0], a3, b0); ffma2(acc[3][1], a3, b1d);
        }
        if (kt + 1 < NT) {
            const int nxt = cur ^ 1;
            As[nxt][ak + 0][ar] = aReg.x; As[nxt][ak + 1][ar] = aReg.y;
            As[nxt][ak + 2][ar] = aReg.z; As[nxt][ak + 3][ar] = aReg.w;
            *(float4*)&Bs[nxt][br][bn4] = bReg;
        }
        __syncthreads();
    }
    const int n = n0 + tn * 2;
    const float bias0 = b1[n], bias1 = b1[n + 1];
    #pragma unroll
    for (int i = 0; i < 4; ++i) {
        float2 c0 = unpack2(acc[i][0]);
        float2 c1 = unpack2(acc[i][1]);
        const int m = m0 + tm * 8 + 2 * i;
        g_tf[(size_t)m * DB + n]           = fmaxf(__fadd_rn(c0.x, bias0), 0.f);
        g_tf[(size_t)m * DB + n + 1]       = fmaxf(__fadd_rn(c1.x, bias1), 0.f);
        g_tf[(size_t)(m + 1) * DB + n]     = fmaxf(__fadd_rn(c0.y, bias0), 0.f);
        g_tf[(size_t)(m + 1) * DB + n + 1] = fmaxf(__fadd_rn(c1.y, bias1), 0.f);
    }
}

/* ---- norms (verified order) + per-row correctly-rounded reciprocal ---- */
__global__ void __launch_bounds__(256) k_norm(const float* __restrict__ hist) {
    __shared__ float tile[8][32][33];
    const int w = threadIdx.x >> 5, lane = threadIdx.x & 31;
    const int row0 = blockIdx.x * 256 + w * 32;
    const float* src = (row0 < BATCH) ? (g_tf + (size_t)row0 * DB)
                                      : (hist + (size_t)(row0 - BATCH) * DB);
    float acc = 0.f;
    for (int ch = 0; ch < 8; ++ch) {
        #pragma unroll 8
        for (int r = 0; r < 32; ++r)
            tile[w][r][lane] = src[(size_t)r * DB + ch * 32 + lane];
        __syncwarp();
        #pragma unroll 8
        for (int j = 0; j < 32; ++j) {
            float v = tile[w][lane][j];
            acc = __fadd_rn(acc, __fmul_rn(v, v));
        }
        __syncwarp();
    }
    const float nm = __fsqrt_rn(acc);
    g_norm[row0 + lane] = nm;
    g_rcp[row0 + lane] = __fdiv_rn(1.0f, __fadd_rn(nm, 1e-12f));
}

/* ---- normalize via Markstein (bit-identical to __fdiv_rn) + scatter ---- */
__global__ void __launch_bounds__(256) k_qnrm(const float* __restrict__ hist) {
    const int gid = blockIdx.x * 256 + threadIdx.x;
    const int r = gid >> 6, q = (gid & 63) << 2;
    const float* src = (r < BATCH) ? (g_tf + (size_t)r * DB)
                                   : (hist + (size_t)(r - BATCH) * DB);
    float4 v = *(const float4*)(src + q);
    const float den = __fadd_rn(g_norm[r], 1e-12f);
    const float y = g_rcp[r];
    float4 o;
    o.x = div_ms(v.x, den, y); o.y = div_ms(v.y, den, y);
    o.z = div_ms(v.z, den, y); o.w = div_ms(v.w, den, y);
    *(float4*)(g_bns + (size_t)g_pos[r] * DB + q) = o;
    if (r < BATCH) *(float4*)(g_qn + (size_t)r * DB + q) = o;
}

/* ---- double class sums over sorted segments ---- */
__global__ void k_gsum() {   /* grid (NC, 8), block 256 */
    const int c = blockIdx.x, p = blockIdx.y, d = threadIdx.x;
    const int lo = g_cofs[c], cnt = g_cofs[c + 1] - lo;
    const int i0 = lo + (int)(((long long)cnt * p) >> 3);
    const int i1 = lo + (int)(((long long)cnt * (p + 1)) >> 3);
    double a0 = 0, a1 = 0, a2 = 0, a3 = 0;
    int i = i0;
    for (; i + 4 <= i1; i += 4) {
        a0 += (double)g_bns[(size_t)i * DB + d];
        a1 += (double)g_bns[(size_t)(i + 1) * DB + d];
        a2 += (double)g_bns[(size_t)(i + 2) * DB + d];
        a3 += (double)g_bns[(size_t)(i + 3) * DB + d];
    }
    for (; i < i1; ++i) a0 += (double)g_bns[(size_t)i * DB + d];
    g_Gp[(p * NC + c) * DB + d] = (a0 + a1) + (a2 + a3);
}

__global__ void k_gred() {   /* grid NC, block 256 */
    const int c = blockIdx.x, d = threadIdx.x;
    double s = 0;
    for (int p = 0; p < 8; ++p) s += g_Gp[(p * NC + c) * DB + d];
    g_Gd[c * DB + d] = s;
}

/* ---- screen: double means + worst-case margins -> contenders ---- */
__global__ void __launch_bounds__(256) k_screen() {  /* grid 256 */
    __shared__ float qs[8][256];
    const int w = threadIdx.x >> 5, lane = threadIdx.x & 31;
    const int b = blockIdx.x * 8 + w;
    for (int j = lane; j < 256; j += 32) qs[w][j] = g_qn[(size_t)b * DB + j];
    __syncwarp();
    double t = 1e300, Mc = 0.0;
    if (lane < NC) {
        const int lo = g_cofs[lane], cnt = g_cofs[lane + 1] - lo;
        if (cnt > 0) {
            const double* G = &g_Gd[lane * DB];
            double a0 = 0, a1 = 0, a2 = 0, a3 = 0;
            #pragma unroll 4
            for (int d = 0; d < 256; d += 4) {
                a0 += (double)qs[w][d]     * G[d];
                a1 += (double)qs[w][d + 1] * G[d + 1];
                a2 += (double)qs[w][d + 2] * G[d + 2];
                a3 += (double)qs[w][d + 3] * G[d + 3];
            }
            double dot = (a0 + a1) + (a2 + a3);
            t = ((double)cnt - dot) / (double)cnt;
            Mc = 6.05e-8 * (double)(cnt + 8) + 2.5e-5;
        }
    }
    double tmin = t, Mmin = Mc;
    #pragma unroll
    for (int off = 16; off; off >>= 1) {
        double ov = __shfl_xor_sync(0xffffffffu, tmin, off);
        double om = __shfl_xor_sync(0xffffffffu, Mmin, off);
        if (ov < tmin) { tmin = ov; Mmin = om; }
    }
    const bool cont = (lane < NC) && (t <= tmin + Mc + Mmin);
    const unsigned mask = __ballot_sync(0xffffffffu, cont);
    g_rex[b * 32 + lane] = __int_as_float(0x7f800000);
    if (__popc(mask) == 1) {
        if (lane == 0) g_ltar[b] = __ffs(mask) - 1;
    } else {
        if (lane == 0) g_ltar[b] = -1;
        if (cont) {
            int k = atomicAdd(&g_nrows[lane], 1);
            g_rowlist[lane * BATCH + k] = b;
        }
    }
}

/* ---- exact pass v2: 32 q-rows/block, double-buffered chunks ----
   Bit-exact: per (b,c) ascending-d __fmaf_rn dot chains, fl(1-dot),
   ascending-segment-order sequential __fadd_rn fold, __fdiv_rn mean.
   float4 decode: row = u>>6 (64 float4 per 256-float row), d4 = (u&63)*4. */
extern __shared__ float dynsm[];
__global__ void __launch_bounds__(256) k_exact() {  /* grid (NC, 64) */
    const int c = blockIdx.x;
    const int nr = g_nrows[c];
    const int q0i = blockIdx.y * QROWS;
    if (q0i >= nr) return;
    float* As = dynsm;                       /* [2][64][STR] */
    float* qs = dynsm + 2 * CHUNK * STR;     /* [32][STR]    */
    float* fb = qs + QROWS * STR;            /* [8][4][64]   */
    const int tid = threadIdx.x;
    const int w = tid >> 5, lane = tid & 31;
    const int lo = g_cofs[c], cnt = g_cofs[c + 1] - lo;

    /* load up to 32 contender q rows */
    for (int u = tid; u < QROWS * 256; u += 256) {
        const int s = u >> 8, d = u & 255;
        const int qi = q0i + s;
        const int b = (qi < nr) ? g_rowlist[c * BATCH + qi] : 0;
        qs[s * STR + d] = g_qn[(size_t)b * DB + d];
    }

    const int nch = (cnt + CHUNK - 1) / CHUNK;
    float4 ld[16];
    /* prologue: chunk 0 into regs then buffer 0 */
    {
        #pragma unroll
        for (int i = 0; i < 16; ++i) {
            const int u = tid + 256 * i;
            const int r = u >> 6, d4 = (u & 63) << 2;
            ld[i] = (r < cnt) ? *(const float4*)&g_bns[(size_t)(lo + r) * DB + d4]
                              : make_float4(0.f, 0.f, 0.f, 0.f);
        }
        #pragma unroll
        for (int i = 0; i < 16; ++i) {
            const int u = tid + 256 * i;
            const int r = u >> 6, d4 = (u & 63) << 2;
            *(float4*)&As[r * STR + d4] = ld[i];
        }
    }
    __syncthreads();

    const int myq = q0i + w * 4 + lane;         /* lane<4: fold row validity */
    const bool foldv = (lane < 4) && (myq < nr);
    float s = 0.f;

    for (int ch = 0; ch < nch; ++ch) {
        const int cur = ch & 1;
        if (ch + 1 < nch) {
            const int base = (ch + 1) * CHUNK;
            #pragma unroll
            for (int i = 0; i < 16; ++i) {
                const int u = tid + 256 * i;
                const int r = base + (u >> 6), d4 = (u & 63) << 2;
                ld[i] = (r < cnt) ? *(const float4*)&g_bns[(size_t)(lo + r) * DB + d4]
                                  : make_float4(0.f, 0.f, 0.f, 0.f);
            }
        }
        int m = cnt - ch * CHUNK;
        if (m > CHUNK) m = CHUNK;
        const float* bufc = As + cur * (CHUNK * STR);
        const bool v0 = lane < m, v1 = lane + 32 < m;
        #pragma unroll
        for (int qi = 0; qi < 4; ++qi) {
            if (q0i + w * 4 + qi < nr) {
                const float* qp = &qs[(w * 4 + qi) * STR];
                const float* r0 = bufc + lane * STR;
                const float* r1 = bufc + (lane + 32) * STR;
                float a0 = 0.f, a1 = 0.f;
                #pragma unroll 8
                for (int d = 0; d < 256; ++d) {
                    a0 = __fmaf_rn(qp[d], r0[d], a0);
                    a1 = __fmaf_rn(qp[d], r1[d], a1);
                }
                if (v0) fb[(w * 4 + qi) * 64 + lane]      = __fadd_rn(1.0f, -a0);
                if (v1) fb[(w * 4 + qi) * 64 + lane + 32] = __fadd_rn(1.0f, -a1);
            }
        }
        __syncwarp();
        if (foldv) {
            const float* f = &fb[(w * 4 + lane) * 64];
            for (int j = 0; j < m; ++j) s = __fadd_rn(s, f[j]);
        }
        __syncwarp();
        if (ch + 1 < nch) {
            float* bufn = As + (cur ^ 1) * (CHUNK * STR);
            #pragma unroll
            for (int i = 0; i < 16; ++i) {
                const int u = tid + 256 * i;
                const int r = u >> 6, d4 = (u & 63) << 2;
                *(float4*)&bufn[r * STR + d4] = ld[i];
            }
        }
        __syncthreads();
    }
    if (foldv) {
        const int b = g_rowlist[c * BATCH + myq];
        g_rex[b * 32 + c] = __fdiv_rn(s, (float)cnt);
    }
}

/* ---- decide: single-contender fast path or exact argmin ---- */
__global__ void __launch_bounds__(256) k_decide(float* __restrict__ out) {
    const int w = threadIdx.x >> 5, lane = threadIdx.x & 31;
    const int b = blockIdx.x * 8 + w;
    int lt = g_ltar[b];
    if (lt < 0) {
        float v = (lane < NC) ? g_rex[b * 32 + lane] : __int_as_float(0x7f800000);
        int idx = lane;
        #pragma unroll
        for (int off = 16; off; off >>= 1) {
            float ov = __shfl_xor_sync(0xffffffffu, v, off);
            int oi = __shfl_xor_sync(0xffffffffu, idx, off);
            if (ov < v || (ov == v && oi < idx)) { v = ov; idx = oi; }
        }
        lt = idx;
        if (lane == 0) g_ltar[b] = lt;
    }
    if (lane == 0) out[BATCH + b] = (float)lt;
}

/* ---- logits, argmax, per-row loss (verified) ---- */
__global__ void __launch_bounds__(256) k_logits(const float* __restrict__ Wc,
                                                const float* __restrict__ bc,
                                                float* __restrict__ out) {
    __shared__ float Ws[DB * 32];
    __shared__ float bcs[32];
    __shared__ float qrow[8][DB];
    const int tid = threadIdx.x;
    for (int i = tid; i < DB * 32; i += 256) {
        int d = i >> 5, c = i & 31;
        Ws[i] = (c < NC) ? Wc[d * NC + c] : 0.f;
    }
    if (tid < 32) bcs[tid] = (tid < NC) ? bc[tid] : 0.f;
    __syncthreads();
    const int w = tid >> 5, lane = tid & 31;
    const int b = blockIdx.x * 8 + w;
    *(float4*)&qrow[w][lane * 8]     = *(const float4*)(g_tf + (size_t)b * DB + lane * 8);
    *(float4*)&qrow[w][lane * 8 + 4] = *(const float4*)(g_tf + (size_t)b * DB + lane * 8 + 4);
    __syncwarp();
    float acc = 0.f;
    #pragma unroll 8
    for (int d = 0; d < DB; ++d) acc = __fmaf_rn(qrow[w][d], Ws[d * 32 + lane], acc);
    float logit = (lane < NC) ? __fadd_rn(acc, bcs[lane]) : -__int_as_float(0x7f800000);
    float v = logit;
    int idx = lane;
    #pragma unroll
    for (int off = 16; off; off >>= 1) {
        float ov = __shfl_xor_sync(0xffffffffu, v, off);
        int oi = __shfl_xor_sync(0xffffffffu, idx, off);
        if (ov > v || (ov == v && oi < idx)) { v = ov; idx = oi; }
    }
    const float m = v;
    float e = (lane < NC) ? expf(logit - m) : 0.f;
    #pragma unroll
    for (int off = 16; off; off >>= 1) e += __shfl_xor_sync(0xffffffffu, e, off);
    const int ltar = g_ltar[b];
    const float lt = __shfl_sync(0xffffffffu, logit, ltar);
    if (lane == 0) {
        out[b] = (float)idx;
        g_loss[b] = (logf(e) + m) - lt;
    }
}

__global__ void __launch_bounds__(256) k_final(float* __restrict__ out) {
    __shared__ float red[256];
    const int tid = threadIdx.x;
    float s = 0.f;
    for (int i = tid; i < BATCH; i += 256) s += g_loss[i];
    red[tid] = s;
    __syncthreads();
    for (int st = 128; st; st >>= 1) {
        if (tid < st) red[tid] += red[tid + st];
        __syncthreads();
    }
    if (tid == 0) out[2 * BATCH] = red[0] / (float)BATCH;
}

extern "C" void kernel_launch(void* const* d_in, const int* in_sizes, int n_in,
                              void* d_out, int out_size) {
    const float* target  = (const float*)d_in[0];
    const int*   curlab  = (const int*)d_in[1];
    const float* hist    = (const float*)d_in[2];
    const int*   histlab = (const int*)d_in[3];
    const float* W1      = (const float*)d_in[4];
    const float* b1      = (const float*)d_in[5];
    const float* Wc      = (const float*)d_in[6];
    const float* bc      = (const float*)d_in[7];
    float* out = (float*)d_out;

    const int exsmem = (2 * CHUNK * STR + QROWS * STR + 8 * 4 * 64) * 4;
    cudaFuncSetAttribute(k_exact, cudaFuncAttributeMaxDynamicSharedMemorySize, exsmem);

    k_init<<<1, 32>>>(curlab);
    k_phist<<<NBANK / 256, 256>>>(curlab, histlab);
    k_pscan<<<1, 32>>>();
    k_pplace<<<NBANK / 256, 256>>>(curlab, histlab);
    dim3 g1(DB / BN, BATCH / BM);
    k_gemm1<<<g1, 256>>>(target, W1, b1);
    k_norm<<<NBANK / 256, 256>>>(hist);
    k_qnrm<<<(NBANK * 64) / 256, 256>>>(hist);
    dim3 gs(NC, 8);
    k_gsum<<<gs, 256>>>();
    k_gred<<<NC, 256>>>();
    k_screen<<<BATCH / 8, 256>>>();
    dim3 ge(NC, 64);
    k_exact<<<ge, 256, exsmem>>>();
    k_decide<<<BATCH / 8, 256>>>(out);
    k_logits<<<BATCH / 8, 256>>>(Wc, bc, out);
    k_final<<<1, 256>>>(out);
}